// round 3
// baseline (speedup 1.0000x reference)
#include <cuda_runtime.h>
#include <math.h>

#define D_MODEL 2048
#define N_HEADS 16
#define HEAD_DIM 128
#define BATCH 2
#define SEQ 2048
#define MROWS (BATCH*SEQ)   /* 4096 */

// Scratch (static device globals: allocation-free per harness rules)
__device__ float g_q[(size_t)MROWS * D_MODEL];
__device__ float g_k[(size_t)MROWS * D_MODEL];
__device__ float g_v[(size_t)MROWS * D_MODEL];
__device__ float g_attn[(size_t)MROWS * D_MODEL];
__device__ int   g_pos[MROWS];

// ---------------------------------------------------------------------------
// Position normalization: reference says int64, but JAX without x64 gives
// int32. Detect layout from the data (int64 -> odd 32-bit words of the first
// 2048 entries are all zero; int32 -> they are sorted random positions) and
// write a clean int32 array. One block, deterministic, capture-safe.
// ---------------------------------------------------------------------------
__global__ __launch_bounds__(1024) void pos_norm_kernel(const int* __restrict__ raw)
{
    __shared__ int s_or[32];
    const int tid = threadIdx.x;
    int any = 0;
    // Only touch words 0..4095 (safe under BOTH layouts).
    for (int i = tid; i < 2048; i += 1024) any |= raw[2 * i + 1];
#pragma unroll
    for (int o = 16; o; o >>= 1) any |= __shfl_down_sync(0xFFFFFFFFu, any, o);
    if ((tid & 31) == 0) s_or[tid >> 5] = any;
    __syncthreads();
    if (tid < 32) {
        int v = s_or[tid];
#pragma unroll
        for (int o = 16; o; o >>= 1) v |= __shfl_down_sync(0xFFFFFFFFu, v, o);
        if (tid == 0) s_or[0] = v;
    }
    __syncthreads();
    const bool is64 = (s_or[0] == 0);
    for (int i = tid; i < MROWS; i += 1024)
        g_pos[i] = is64 ? raw[2 * i] : raw[i];
}

// ---------------------------------------------------------------------------
// SGEMM: C[M,N] = A[M,K] @ B[K,N], fp32. 128x128 block, BK=8, 8x8 per thread.
// ---------------------------------------------------------------------------
__global__ __launch_bounds__(256) void sgemm128(const float* __restrict__ A,
                                                const float* __restrict__ B,
                                                float* __restrict__ C,
                                                int M, int N, int K)
{
    constexpr int BM = 128, BN = 128, BK = 8, TM = 8, TN = 8;
    __shared__ float As[BK][BM];
    __shared__ float Bs[BK][BN];

    const int tid  = threadIdx.x;
    const int trow = tid >> 4;
    const int tcol = tid & 15;
    const int rowStart = blockIdx.y * BM;
    const int colStart = blockIdx.x * BN;

    const int aRow = tid >> 1;
    const int aCol = (tid & 1) << 2;
    const int bRow = tid >> 5;
    const int bCol = (tid & 31) << 2;

    float acc[TM][TN];
#pragma unroll
    for (int i = 0; i < TM; i++)
#pragma unroll
        for (int j = 0; j < TN; j++) acc[i][j] = 0.0f;

    const float* Ab = A + (size_t)(rowStart) * K;
    const float* Bb = B + colStart;

    for (int k0 = 0; k0 < K; k0 += BK) {
        float4 a4 = *(const float4*)(Ab + (size_t)aRow * K + k0 + aCol);
        As[aCol + 0][aRow] = a4.x;
        As[aCol + 1][aRow] = a4.y;
        As[aCol + 2][aRow] = a4.z;
        As[aCol + 3][aRow] = a4.w;
        float4 b4 = *(const float4*)(Bb + (size_t)(k0 + bRow) * N + bCol);
        *(float4*)&Bs[bRow][bCol] = b4;
        __syncthreads();

#pragma unroll
        for (int kk = 0; kk < BK; kk++) {
            float ar[TM], br[TN];
#pragma unroll
            for (int i = 0; i < TM; i++) ar[i] = As[kk][trow * TM + i];
#pragma unroll
            for (int j = 0; j < TN; j++) br[j] = Bs[kk][tcol * TN + j];
#pragma unroll
            for (int i = 0; i < TM; i++)
#pragma unroll
                for (int j = 0; j < TN; j++)
                    acc[i][j] += ar[i] * br[j];
        }
        __syncthreads();
    }

#pragma unroll
    for (int i = 0; i < TM; i++) {
        float* cp = C + (size_t)(rowStart + trow * TM + i) * N + colStart + tcol * TN;
        float4 v0 = make_float4(acc[i][0], acc[i][1], acc[i][2], acc[i][3]);
        float4 v1 = make_float4(acc[i][4], acc[i][5], acc[i][6], acc[i][7]);
        *(float4*)(cp)     = v0;
        *(float4*)(cp + 4) = v1;
    }
}

// ---------------------------------------------------------------------------
// RoPE, in-place on Q and K ([b,s,h,d] layout = row-major [MROWS, D_MODEL]).
// Angle computed in fp32 exactly like the reference (fp32 inv_freq, fp32
// product), then accurate sincos of that fp32 angle.
// ---------------------------------------------------------------------------
__global__ __launch_bounds__(256) void rope_kernel(float* __restrict__ q,
                                                   float* __restrict__ k)
{
    int idx = blockIdx.x * 256 + threadIdx.x;   // total = MROWS*N_HEADS*64
    int d  = idx & 63;
    int h  = (idx >> 6) & 15;
    int bs = idx >> 10;

    float invf = 1.0f / powf(10000.0f, (float)d * (1.0f / 64.0f));
    float angf = (float)g_pos[bs] * invf;
    double sa, ca;
    sincos((double)angf, &sa, &ca);
    float c = (float)ca, s = (float)sa;

    size_t base = (size_t)bs * D_MODEL + h * HEAD_DIM;
    float q1 = q[base + d], q2 = q[base + d + 64];
    q[base + d]      = q1 * c - q2 * s;
    q[base + d + 64] = q2 * c + q1 * s;
    float k1 = k[base + d], k2 = k[base + d + 64];
    k[base + d]      = k1 * c - k2 * s;
    k[base + d + 64] = k2 * c + k1 * s;
}

// ---------------------------------------------------------------------------
// Flash-style attention. One CTA = one (b,h) and a 64-row q tile.
// Online softmax; O accumulators in registers (4 rows x 8 cols per thread).
// Mask: pos_q >= pos_k (sorted positions -> every row has its diagonal).
// ---------------------------------------------------------------------------
constexpr int BQ = 64, BKV = 64;
constexpr int PADQ = 129, PADK = 129, PADV = 132, PADS = 65;
constexpr int ATTN_SMEM =
    (2 * 64 * 4) + (3 * 64 * 4) + BQ * PADS * 4 + BQ * PADQ * 4 +
    BKV * PADK * 4 + BKV * PADV * 4;   // 117760 bytes

__global__ __launch_bounds__(256) void attn64(const float* __restrict__ Q,
                                              const float* __restrict__ K,
                                              const float* __restrict__ V,
                                              float* __restrict__ O)
{
    extern __shared__ char smraw[];
    int* posq = (int*)smraw;
    int* posk = posq + 64;
    float* m     = (float*)(posk + 64);
    float* l     = m + 64;
    float* alpha = l + 64;
    float* sS = alpha + 64;
    float* sQ = sS + BQ * PADS;
    float* sK = sQ + BQ * PADQ;
    float* sV = sK + BKV * PADK;

    const int qt = blockIdx.x;           // 0..31
    const int bh = blockIdx.y;           // 0..31
    const int b  = bh >> 4, h = bh & 15;
    const int tid = threadIdx.x;
    const int ty = tid >> 4, tx = tid & 15;

    const size_t rowQ0 = (size_t)b * SEQ + qt * BQ;
    const float* Qb = Q + rowQ0 * D_MODEL + h * HEAD_DIM;
    const int* posB = g_pos + (size_t)b * SEQ;

    for (int t = 0; t < 32; t++) {
        int idx = t * 256 + tid;
        int r = idx >> 7, c = idx & 127;
        sQ[r * PADQ + c] = Qb[(size_t)r * D_MODEL + c];
    }
    if (tid < 64) {
        posq[tid] = posB[qt * BQ + tid];
        m[tid] = -INFINITY;
        l[tid] = 0.0f;
    }

    float o[4][8];
#pragma unroll
    for (int i = 0; i < 4; i++)
#pragma unroll
        for (int j = 0; j < 8; j++) o[i][j] = 0.0f;

    const float scale = 0.08838834764831845f;   // 1/sqrt(128)

    for (int kt = 0; kt < SEQ / BKV; kt++) {
        __syncthreads();   // protects K/V overwrite vs prev O-update (and Q load)
        const float* Kb = K + ((size_t)b * SEQ + kt * BKV) * D_MODEL + h * HEAD_DIM;
        const float* Vb = V + ((size_t)b * SEQ + kt * BKV) * D_MODEL + h * HEAD_DIM;
        for (int t = 0; t < 32; t++) {
            int idx = t * 256 + tid;
            int r = idx >> 7, c = idx & 127;
            sK[r * PADK + c] = Kb[(size_t)r * D_MODEL + c];
            sV[r * PADV + c] = Vb[(size_t)r * D_MODEL + c];
        }
        if (tid >= 64 && tid < 128) posk[tid - 64] = posB[kt * BKV + (tid - 64)];
        __syncthreads();

        // S = Q K^T (4x4 per thread)
        float acc[4][4];
#pragma unroll
        for (int i = 0; i < 4; i++)
#pragma unroll
            for (int j = 0; j < 4; j++) acc[i][j] = 0.0f;

#pragma unroll 4
        for (int d = 0; d < HEAD_DIM; d++) {
            float qr[4], kc[4];
#pragma unroll
            for (int i = 0; i < 4; i++) qr[i] = sQ[(ty * 4 + i) * PADQ + d];
#pragma unroll
            for (int j = 0; j < 4; j++) kc[j] = sK[(tx * 4 + j) * PADK + d];
#pragma unroll
            for (int i = 0; i < 4; i++)
#pragma unroll
                for (int j = 0; j < 4; j++)
                    acc[i][j] += qr[i] * kc[j];
        }
#pragma unroll
        for (int i = 0; i < 4; i++) {
            int r = ty * 4 + i;
            int pq = posq[r];
#pragma unroll
            for (int j = 0; j < 4; j++) {
                int c = tx * 4 + j;
                float s = (pq >= posk[c]) ? acc[i][j] * scale : -1e30f;
                sS[r * PADS + c] = s;
            }
        }
        __syncthreads();

        // Online softmax row stats (one thread per row)
        if (tid < 64) {
            int r = tid;
            float mx = -INFINITY;
            for (int c = 0; c < BKV; c++) mx = fmaxf(mx, sS[r * PADS + c]);
            float nm = fmaxf(m[r], mx);
            float al = expf(m[r] - nm);
            float sum = 0.0f;
            for (int c = 0; c < BKV; c++) {
                float p = expf(sS[r * PADS + c] - nm);
                sS[r * PADS + c] = p;
                sum += p;
            }
            l[r] = l[r] * al + sum;
            m[r] = nm;
            alpha[r] = al;
        }
        __syncthreads();

        // O = O*alpha + P @ V
#pragma unroll
        for (int i = 0; i < 4; i++) {
            float al = alpha[ty * 4 + i];
#pragma unroll
            for (int j = 0; j < 8; j++) o[i][j] *= al;
        }
        for (int k = 0; k < BKV; k++) {
            float p[4];
#pragma unroll
            for (int i = 0; i < 4; i++) p[i] = sS[(ty * 4 + i) * PADS + k];
            float4 v0 = *(float4*)&sV[k * PADV + tx * 8];
            float4 v1 = *(float4*)&sV[k * PADV + tx * 8 + 4];
#pragma unroll
            for (int i = 0; i < 4; i++) {
                o[i][0] += p[i] * v0.x;  o[i][1] += p[i] * v0.y;
                o[i][2] += p[i] * v0.z;  o[i][3] += p[i] * v0.w;
                o[i][4] += p[i] * v1.x;  o[i][5] += p[i] * v1.y;
                o[i][6] += p[i] * v1.z;  o[i][7] += p[i] * v1.w;
            }
        }
    }

    // Final normalize + write ([b,s,h,d] layout)
    float* Ob = O + rowQ0 * D_MODEL + h * HEAD_DIM;
#pragma unroll
    for (int i = 0; i < 4; i++) {
        int r = ty * 4 + i;
        float inv = 1.0f / l[r];
        float* op = Ob + (size_t)r * D_MODEL + tx * 8;
#pragma unroll
        for (int j = 0; j < 8; j++) op[j] = o[i][j] * inv;
    }
}

// ---------------------------------------------------------------------------
extern "C" void kernel_launch(void* const* d_in, const int* in_sizes, int n_in,
                              void* d_out, int out_size)
{
    // Resolve slots by size (x=8388608 unique, pos=4096 unique).
    int idx_x = -1, idx_pos = -1;
    for (int i = 0; i < n_in; i++) {
        if (in_sizes[i] == MROWS * D_MODEL) idx_x = i;
        if (in_sizes[i] == MROWS)           idx_pos = i;
    }

    const float* x;
    const float *wq, *wk, *wv, *wo;
    const int* posraw;

    if (idx_x == 0) {   // dict order: x, Wq, Wk, Wv, Wo, pos
        x  = (const float*)d_in[0];
        wq = (const float*)d_in[1];
        wk = (const float*)d_in[2];
        wv = (const float*)d_in[3];
        wo = (const float*)d_in[4];
        posraw = (const int*)d_in[idx_pos >= 0 ? idx_pos : 5];
    } else {            // alphabetical: Wk, Wo, Wq, Wv, pos, x
        wk = (const float*)d_in[0];
        wo = (const float*)d_in[1];
        wq = (const float*)d_in[2];
        wv = (const float*)d_in[3];
        posraw = (const int*)d_in[idx_pos >= 0 ? idx_pos : 4];
        x  = (const float*)d_in[idx_x >= 0 ? idx_x : 5];
    }

    float* out = (float*)d_out;

    float *q, *k, *v, *a;
    cudaGetSymbolAddress((void**)&q, g_q);
    cudaGetSymbolAddress((void**)&k, g_k);
    cudaGetSymbolAddress((void**)&v, g_v);
    cudaGetSymbolAddress((void**)&a, g_attn);

    cudaFuncSetAttribute(attn64, cudaFuncAttributeMaxDynamicSharedMemorySize, ATTN_SMEM);

    pos_norm_kernel<<<1, 1024>>>(posraw);

    dim3 gProj(D_MODEL / 128, MROWS / 128);
    sgemm128<<<gProj, 256>>>(x, wq, q, MROWS, D_MODEL, D_MODEL);
    sgemm128<<<gProj, 256>>>(x, wk, k, MROWS, D_MODEL, D_MODEL);
    sgemm128<<<gProj, 256>>>(x, wv, v, MROWS, D_MODEL, D_MODEL);

    rope_kernel<<<(MROWS * N_HEADS * 64) / 256, 256>>>(q, k);

    attn64<<<dim3(SEQ / BQ, BATCH * N_HEADS), 256, ATTN_SMEM>>>(q, k, v, a);

    sgemm128<<<gProj, 256>>>(a, wo, out, MROWS, D_MODEL, D_MODEL);
}

// round 9
// speedup vs baseline: 1.6207x; 1.6207x over previous
#include <cuda_runtime.h>
#include <cuda_bf16.h>
#include <math.h>
#include <stdint.h>

#define D_MODEL 2048
#define N_HEADS 16
#define HEAD_DIM 128
#define BATCH 2
#define SEQ 2048
#define MROWS (BATCH*SEQ)   /* 4096 */

// ---------------------------------------------------------------------------
// Scratch (static device globals: allocation-free per harness rules)
// ---------------------------------------------------------------------------
__device__ float g_q[(size_t)MROWS * D_MODEL];
__device__ float g_k[(size_t)MROWS * D_MODEL];
__device__ float g_v[(size_t)MROWS * D_MODEL];
__device__ float g_attn[(size_t)MROWS * D_MODEL];
__device__ int   g_pos[MROWS];

__device__ __nv_bfloat16 g_xhi[(size_t)MROWS * D_MODEL];
__device__ __nv_bfloat16 g_xlo[(size_t)MROWS * D_MODEL];
__device__ __nv_bfloat16 g_ahi[(size_t)MROWS * D_MODEL];
__device__ __nv_bfloat16 g_alo[(size_t)MROWS * D_MODEL];
__device__ __nv_bfloat16 g_wThi[4][(size_t)D_MODEL * D_MODEL];
__device__ __nv_bfloat16 g_wTlo[4][(size_t)D_MODEL * D_MODEL];

// ---------------------------------------------------------------------------
// Helpers (baseline PTX only: works on .target sm_103)
// ---------------------------------------------------------------------------
__device__ __forceinline__ uint32_t smem_to_u32(const void* p) {
    uint32_t a;
    asm("{ .reg .u64 t; cvta.to.shared.u64 t, %1; cvt.u32.u64 %0, t; }"
        : "=r"(a) : "l"(p));
    return a;
}
#define SMEM_SWIZZLE_128B(off) ((off) ^ (((off) >> 3) & 0x70))

__device__ __forceinline__ void ldsm_x4(uint32_t* r, uint32_t addr) {
    asm volatile("ldmatrix.sync.aligned.m8n8.x4.shared.b16 {%0,%1,%2,%3}, [%4];"
        : "=r"(r[0]), "=r"(r[1]), "=r"(r[2]), "=r"(r[3]) : "r"(addr));
}
__device__ __forceinline__ void mma16816(float* c, const uint32_t* a, const uint32_t* b) {
    asm volatile("mma.sync.aligned.m16n8k16.row.col.f32.bf16.bf16.f32 "
        "{%0,%1,%2,%3}, {%4,%5,%6,%7}, {%8,%9}, {%0,%1,%2,%3};"
        : "+f"(c[0]), "+f"(c[1]), "+f"(c[2]), "+f"(c[3])
        : "r"(a[0]), "r"(a[1]), "r"(a[2]), "r"(a[3]), "r"(b[0]), "r"(b[1]));
}
#define CP_ASYNC16(sm, gp) \
    asm volatile("cp.async.cg.shared.global [%0], [%1], 16;" :: "r"(sm), "l"(gp))
#define CP_COMMIT() asm volatile("cp.async.commit_group;" ::: "memory")
#define CP_WAIT1()  asm volatile("cp.async.wait_group 1;" ::: "memory")

// ---------------------------------------------------------------------------
// Position normalization (int64-vs-int32 dtype detection)
// ---------------------------------------------------------------------------
__global__ __launch_bounds__(1024) void pos_norm_kernel(const int* __restrict__ raw)
{
    __shared__ int s_or[32];
    const int tid = threadIdx.x;
    int any = 0;
    for (int i = tid; i < 2048; i += 1024) any |= raw[2 * i + 1];
#pragma unroll
    for (int o = 16; o; o >>= 1) any |= __shfl_down_sync(0xFFFFFFFFu, any, o);
    if ((tid & 31) == 0) s_or[tid >> 5] = any;
    __syncthreads();
    if (tid < 32) {
        int v = s_or[tid];
#pragma unroll
        for (int o = 16; o; o >>= 1) v |= __shfl_down_sync(0xFFFFFFFFu, v, o);
        if (tid == 0) s_or[0] = v;
    }
    __syncthreads();
    const bool is64 = (s_or[0] == 0);
    for (int i = tid; i < MROWS; i += 1024)
        g_pos[i] = is64 ? raw[2 * i] : raw[i];
}

// ---------------------------------------------------------------------------
// fp32 -> (hi, lo) bf16 split, elementwise
// ---------------------------------------------------------------------------
__global__ __launch_bounds__(256) void split_fp32(const float* __restrict__ in,
                                                  __nv_bfloat16* __restrict__ hi,
                                                  __nv_bfloat16* __restrict__ lo)
{
    int i = blockIdx.x * 256 + threadIdx.x;
    float v = in[i];
    __nv_bfloat16 h = __float2bfloat16(v);
    hi[i] = h;
    lo[i] = __float2bfloat16(v - __bfloat162float(h));
}

// ---------------------------------------------------------------------------
// W[K][N] fp32 -> W^T[N][K] (hi, lo) bf16 split
// ---------------------------------------------------------------------------
__global__ __launch_bounds__(256) void transpose_split(const float* __restrict__ W,
                                                       __nv_bfloat16* __restrict__ hiT,
                                                       __nv_bfloat16* __restrict__ loT)
{
    __shared__ float t[32][33];
    const int n0 = blockIdx.x * 32, k0 = blockIdx.y * 32;
    const int tx = threadIdx.x & 31, ty = threadIdx.x >> 5;
#pragma unroll
    for (int r = ty; r < 32; r += 8)
        t[r][tx] = W[(size_t)(k0 + r) * D_MODEL + n0 + tx];
    __syncthreads();
#pragma unroll
    for (int r = ty; r < 32; r += 8) {
        float v = t[tx][r];
        __nv_bfloat16 h = __float2bfloat16(v);
        size_t o = (size_t)(n0 + r) * D_MODEL + k0 + tx;
        hiT[o] = h;
        loT[o] = __float2bfloat16(v - __bfloat162float(h));
    }
}

// ---------------------------------------------------------------------------
// mma.sync bf16 split GEMM:
//   C[M,N] = (Ahi+Alo)[M,K] @ (Bhi+Blo)[N,K]^T   (B given K-major, i.e. W^T)
// 128x128 CTA tile, BK=64, 3-stage cp.async pipeline, 8 warps (2x4),
// warp tile 64x32, m16n8k16, 3 split terms (hi*hi + hi*lo + lo*hi).
// ---------------------------------------------------------------------------
constexpr int GSTAGES = 3;
constexpr int GT_BYTES = 128 * 64 * 2;            // 16KB per tensor tile
constexpr int GSTAGE_BYTES = 4 * GT_BYTES;        // 64KB per stage
constexpr int GEMM_SMEM = GSTAGES * GSTAGE_BYTES; // 192KB

__device__ __forceinline__ void g_load_stage(uint32_t smst,
                                             const __nv_bfloat16* __restrict__ Ahi,
                                             const __nv_bfloat16* __restrict__ Alo,
                                             const __nv_bfloat16* __restrict__ Bhi,
                                             const __nv_bfloat16* __restrict__ Blo,
                                             int tileM, int tileN, int K, int kc, int tid)
{
    const __nv_bfloat16* gsrc[4];
    gsrc[0] = Ahi + (size_t)tileM * K + kc * 64;
    gsrc[1] = Alo + (size_t)tileM * K + kc * 64;
    gsrc[2] = Bhi + (size_t)tileN * K + kc * 64;
    gsrc[3] = Blo + (size_t)tileN * K + kc * 64;
    const size_t rs = (size_t)K * 2;
#pragma unroll
    for (int tsr = 0; tsr < 4; tsr++) {
        const char* gb = (const char*)gsrc[tsr];
        uint32_t sbase = smst + tsr * GT_BYTES;
#pragma unroll
        for (int it = 0; it < 4; it++) {
            int idx = it * 256 + tid;
            int r = idx >> 3, g = idx & 7;
            uint32_t so = sbase + SMEM_SWIZZLE_128B(r * 128 + g * 16);
            const char* gp = gb + (size_t)r * rs + g * 16;
            CP_ASYNC16(so, gp);
        }
    }
}

__global__ __launch_bounds__(256) void gemm_mma(const __nv_bfloat16* __restrict__ Ahi,
                                                const __nv_bfloat16* __restrict__ Alo,
                                                const __nv_bfloat16* __restrict__ Bhi,
                                                const __nv_bfloat16* __restrict__ Blo,
                                                float* __restrict__ C,
                                                int M, int N, int K)
{
    extern __shared__ char sm[];
    const uint32_t smb = smem_to_u32(sm);
    const int tid = threadIdx.x;
    const int wid = tid >> 5, lane = tid & 31;
    const int warp_m = wid & 1;          // 0..1 -> 64-row slab
    const int warp_n = wid >> 1;         // 0..3 -> 32-col slab
    const int tileN = blockIdx.x * 128, tileM = blockIdx.y * 128;

    float acc[4][4][4];
#pragma unroll
    for (int a = 0; a < 4; a++)
#pragma unroll
        for (int b = 0; b < 4; b++)
#pragma unroll
            for (int c = 0; c < 4; c++) acc[a][b][c] = 0.0f;

    const int niter = K / 64;            // 32

    g_load_stage(smb + 0 * GSTAGE_BYTES, Ahi, Alo, Bhi, Blo, tileM, tileN, K, 0, tid);
    CP_COMMIT();
    g_load_stage(smb + 1 * GSTAGE_BYTES, Ahi, Alo, Bhi, Blo, tileM, tileN, K, 1, tid);
    CP_COMMIT();

    // lane-dependent ldmatrix offsets (within a 128x64-half tile, 128B rows)
    const int a_r = (lane & 7) + ((lane >> 3) & 1) * 8;   // row within 16-row A tile
    const int a_c = (lane >> 4) * 8;                      // 0 or 8 halves
    const int b_r = (lane & 7) + ((lane >> 4) & 1) * 8;   // row within 16-row B pair
    const int b_c = ((lane >> 3) & 1) * 8;

    for (int i = 0; i < niter; i++) {
        CP_WAIT1();
        __syncthreads();

        if (i + 2 < niter)
            g_load_stage(smb + ((i + 2) % GSTAGES) * GSTAGE_BYTES,
                         Ahi, Alo, Bhi, Blo, tileM, tileN, K, i + 2, tid);
        CP_COMMIT();

        const uint32_t st = smb + (i % GSTAGES) * GSTAGE_BYTES;
        const uint32_t aHiB = st, aLoB = st + GT_BYTES;
        const uint32_t bHiB = st + 2 * GT_BYTES, bLoB = st + 3 * GT_BYTES;

#pragma unroll
        for (int ks = 0; ks < 4; ks++) {
            const int kb = ks * 16;
            // B fragments: 4 n-tiles (two x4 loads each for hi and lo)
            uint32_t bh[4][2], bl[4][2];
#pragma unroll
            for (int np = 0; np < 2; np++) {
                const int n_base = warp_n * 32 + np * 16;
                uint32_t off = SMEM_SWIZZLE_128B((n_base + b_r) * 128 + (kb + b_c) * 2);
                uint32_t r4[4];
                ldsm_x4(r4, bHiB + off);
                bh[np * 2][0] = r4[0]; bh[np * 2][1] = r4[1];
                bh[np * 2 + 1][0] = r4[2]; bh[np * 2 + 1][1] = r4[3];
                ldsm_x4(r4, bLoB + off);
                bl[np * 2][0] = r4[0]; bl[np * 2][1] = r4[1];
                bl[np * 2 + 1][0] = r4[2]; bl[np * 2 + 1][1] = r4[3];
            }
            // A tiles: for each of 4 m-tiles, hi+lo fragments, then 12 MMAs
#pragma unroll
            for (int mt = 0; mt < 4; mt++) {
                const int m_base = warp_m * 64 + mt * 16;
                uint32_t off = SMEM_SWIZZLE_128B((m_base + a_r) * 128 + (kb + a_c) * 2);
                uint32_t ah[4], al[4];
                ldsm_x4(ah, aHiB + off);
                ldsm_x4(al, aLoB + off);
#pragma unroll
                for (int nt = 0; nt < 4; nt++) {
                    mma16816(acc[mt][nt], ah, bh[nt]);   // hi*hi
                    mma16816(acc[mt][nt], ah, bl[nt]);   // hi*lo
                    mma16816(acc[mt][nt], al, bh[nt]);   // lo*hi
                }
            }
        }
    }

    // Epilogue: c-fragment -> global fp32
    const int er = lane >> 2;            // 0..7
    const int ec = (lane & 3) * 2;       // 0,2,4,6
#pragma unroll
    for (int mt = 0; mt < 4; mt++) {
        const int row0 = tileM + warp_m * 64 + mt * 16 + er;
#pragma unroll
        for (int nt = 0; nt < 4; nt++) {
            const int col = tileN + warp_n * 32 + nt * 8 + ec;
            float* p0 = C + (size_t)row0 * N + col;
            float* p1 = C + (size_t)(row0 + 8) * N + col;
            *(float2*)p0 = make_float2(acc[mt][nt][0], acc[mt][nt][1]);
            *(float2*)p1 = make_float2(acc[mt][nt][2], acc[mt][nt][3]);
        }
    }
}

// ---------------------------------------------------------------------------
// RoPE, in-place on Q and K
// ---------------------------------------------------------------------------
__global__ __launch_bounds__(256) void rope_kernel(float* __restrict__ q,
                                                   float* __restrict__ k)
{
    int idx = blockIdx.x * 256 + threadIdx.x;
    int d  = idx & 63;
    int h  = (idx >> 6) & 15;
    int bs = idx >> 10;

    float invf = 1.0f / powf(10000.0f, (float)d * (1.0f / 64.0f));
    float angf = (float)g_pos[bs] * invf;
    double sa, ca;
    sincos((double)angf, &sa, &ca);
    float c = (float)ca, s = (float)sa;

    size_t base = (size_t)bs * D_MODEL + h * HEAD_DIM;
    float q1 = q[base + d], q2 = q[base + d + 64];
    q[base + d]      = q1 * c - q2 * s;
    q[base + d + 64] = q2 * c + q1 * s;
    float k1 = k[base + d], k2 = k[base + d + 64];
    k[base + d]      = k1 * c - k2 * s;
    k[base + d + 64] = k2 * c + k1 * s;
}

// ---------------------------------------------------------------------------
// Flash-style attention (unchanged from R3 passing version)
// ---------------------------------------------------------------------------
constexpr int BQ = 64, BKV = 64;
constexpr int PADQ = 129, PADK = 129, PADV = 132, PADS = 65;
constexpr int ATTN_SMEM =
    (2 * 64 * 4) + (3 * 64 * 4) + BQ * PADS * 4 + BQ * PADQ * 4 +
    BKV * PADK * 4 + BKV * PADV * 4;

__global__ __launch_bounds__(256) void attn64(const float* __restrict__ Q,
                                              const float* __restrict__ K,
                                              const float* __restrict__ V,
                                              float* __restrict__ O)
{
    extern __shared__ char smraw[];
    int* posq = (int*)smraw;
    int* posk = posq + 64;
    float* m     = (float*)(posk + 64);
    float* l     = m + 64;
    float* alpha = l + 64;
    float* sS = alpha + 64;
    float* sQ = sS + BQ * PADS;
    float* sK = sQ + BQ * PADQ;
    float* sV = sK + BKV * PADK;

    const int qt = blockIdx.x;
    const int bh = blockIdx.y;
    const int b  = bh >> 4, h = bh & 15;
    const int tid = threadIdx.x;
    const int ty = tid >> 4, tx = tid & 15;

    const size_t rowQ0 = (size_t)b * SEQ + qt * BQ;
    const float* Qb = Q + rowQ0 * D_MODEL + h * HEAD_DIM;
    const int* posB = g_pos + (size_t)b * SEQ;

    for (int t = 0; t < 32; t++) {
        int idx = t * 256 + tid;
        int r = idx >> 7, c = idx & 127;
        sQ[r * PADQ + c] = Qb[(size_t)r * D_MODEL + c];
    }
    if (tid < 64) {
        posq[tid] = posB[qt * BQ + tid];
        m[tid] = -INFINITY;
        l[tid] = 0.0f;
    }

    float o[4][8];
#pragma unroll
    for (int i = 0; i < 4; i++)
#pragma unroll
        for (int j = 0; j < 8; j++) o[i][j] = 0.0f;

    const float scale = 0.08838834764831845f;

    for (int kt = 0; kt < SEQ / BKV; kt++) {
        __syncthreads();
        const float* Kb = K + ((size_t)b * SEQ + kt * BKV) * D_MODEL + h * HEAD_DIM;
        const float* Vb = V + ((size_t)b * SEQ + kt * BKV) * D_MODEL + h * HEAD_DIM;
        for (int t = 0; t < 32; t++) {
            int idx = t * 256 + tid;
            int r = idx >> 7, c = idx & 127;
            sK[r * PADK + c] = Kb[(size_t)r * D_MODEL + c];
            sV[r * PADV + c] = Vb[(size_t)r * D_MODEL + c];
        }
        if (tid >= 64 && tid < 128) posk[tid - 64] = posB[kt * BKV + (tid - 64)];
        __syncthreads();

        float acc[4][4];
#pragma unroll
        for (int i = 0; i < 4; i++)
#pragma unroll
            for (int j = 0; j < 4; j++) acc[i][j] = 0.0f;

#pragma unroll 4
        for (int d = 0; d < HEAD_DIM; d++) {
            float qr[4], kc[4];
#pragma unroll
            for (int i = 0; i < 4; i++) qr[i] = sQ[(ty * 4 + i) * PADQ + d];
#pragma unroll
            for (int j = 0; j < 4; j++) kc[j] = sK[(tx * 4 + j) * PADK + d];
#pragma unroll
            for (int i = 0; i < 4; i++)
#pragma unroll
                for (int j = 0; j < 4; j++)
                    acc[i][j] += qr[i] * kc[j];
        }
#pragma unroll
        for (int i = 0; i < 4; i++) {
            int r = ty * 4 + i;
            int pq = posq[r];
#pragma unroll
            for (int j = 0; j < 4; j++) {
                int c = tx * 4 + j;
                float s = (pq >= posk[c]) ? acc[i][j] * scale : -1e30f;
                sS[r * PADS + c] = s;
            }
        }
        __syncthreads();

        if (tid < 64) {
            int r = tid;
            float mx = -INFINITY;
            for (int c = 0; c < BKV; c++) mx = fmaxf(mx, sS[r * PADS + c]);
            float nm = fmaxf(m[r], mx);
            float al = expf(m[r] - nm);
            float sum = 0.0f;
            for (int c = 0; c < BKV; c++) {
                float p = expf(sS[r * PADS + c] - nm);
                sS[r * PADS + c] = p;
                sum += p;
            }
            l[r] = l[r] * al + sum;
            m[r] = nm;
            alpha[r] = al;
        }
        __syncthreads();

#pragma unroll
        for (int i = 0; i < 4; i++) {
            float al = alpha[ty * 4 + i];
#pragma unroll
            for (int j = 0; j < 8; j++) o[i][j] *= al;
        }
        for (int k = 0; k < BKV; k++) {
            float p[4];
#pragma unroll
            for (int i = 0; i < 4; i++) p[i] = sS[(ty * 4 + i) * PADS + k];
            float4 v0 = *(float4*)&sV[k * PADV + tx * 8];
            float4 v1 = *(float4*)&sV[k * PADV + tx * 8 + 4];
#pragma unroll
            for (int i = 0; i < 4; i++) {
                o[i][0] += p[i] * v0.x;  o[i][1] += p[i] * v0.y;
                o[i][2] += p[i] * v0.z;  o[i][3] += p[i] * v0.w;
                o[i][4] += p[i] * v1.x;  o[i][5] += p[i] * v1.y;
                o[i][6] += p[i] * v1.z;  o[i][7] += p[i] * v1.w;
            }
        }
    }

    float* Ob = O + rowQ0 * D_MODEL + h * HEAD_DIM;
#pragma unroll
    for (int i = 0; i < 4; i++) {
        int r = ty * 4 + i;
        float inv = 1.0f / l[r];
        float* op = Ob + (size_t)r * D_MODEL + tx * 8;
#pragma unroll
        for (int j = 0; j < 8; j++) op[j] = o[i][j] * inv;
    }
}

// ---------------------------------------------------------------------------
extern "C" void kernel_launch(void* const* d_in, const int* in_sizes, int n_in,
                              void* d_out, int out_size)
{
    int idx_x = -1, idx_pos = -1;
    for (int i = 0; i < n_in; i++) {
        if (in_sizes[i] == MROWS * D_MODEL) idx_x = i;
        if (in_sizes[i] == MROWS)           idx_pos = i;
    }

    const float* x;
    const float *wq, *wk, *wv, *wo;
    const int* posraw;

    if (idx_x == 0) {   // dict order: x, Wq, Wk, Wv, Wo, pos
        x  = (const float*)d_in[0];
        wq = (const float*)d_in[1];
        wk = (const float*)d_in[2];
        wv = (const float*)d_in[3];
        wo = (const float*)d_in[4];
        posraw = (const int*)d_in[idx_pos >= 0 ? idx_pos : 5];
    } else {            // alphabetical: Wk, Wo, Wq, Wv, pos, x
        wk = (const float*)d_in[0];
        wo = (const float*)d_in[1];
        wq = (const float*)d_in[2];
        wv = (const float*)d_in[3];
        posraw = (const int*)d_in[idx_pos >= 0 ? idx_pos : 4];
        x  = (const float*)d_in[idx_x >= 0 ? idx_x : 5];
    }

    float* out = (float*)d_out;

    float *q, *k, *v, *a;
    cudaGetSymbolAddress((void**)&q, g_q);
    cudaGetSymbolAddress((void**)&k, g_k);
    cudaGetSymbolAddress((void**)&v, g_v);
    cudaGetSymbolAddress((void**)&a, g_attn);
    __nv_bfloat16 *xhi, *xlo, *ahi, *alo, *wThi, *wTlo;
    cudaGetSymbolAddress((void**)&xhi, g_xhi);
    cudaGetSymbolAddress((void**)&xlo, g_xlo);
    cudaGetSymbolAddress((void**)&ahi, g_ahi);
    cudaGetSymbolAddress((void**)&alo, g_alo);
    cudaGetSymbolAddress((void**)&wThi, g_wThi);
    cudaGetSymbolAddress((void**)&wTlo, g_wTlo);
    const size_t WSZ = (size_t)D_MODEL * D_MODEL;

    cudaFuncSetAttribute(attn64, cudaFuncAttributeMaxDynamicSharedMemorySize, ATTN_SMEM);
    cudaFuncSetAttribute(gemm_mma, cudaFuncAttributeMaxDynamicSharedMemorySize, GEMM_SMEM);

    pos_norm_kernel<<<1, 1024>>>(posraw);

    // Operand conversion
    split_fp32<<<(MROWS * D_MODEL) / 256, 256>>>(x, xhi, xlo);
    dim3 gT(D_MODEL / 32, D_MODEL / 32);
    transpose_split<<<gT, 256>>>(wq, wThi + 0 * WSZ, wTlo + 0 * WSZ);
    transpose_split<<<gT, 256>>>(wk, wThi + 1 * WSZ, wTlo + 1 * WSZ);
    transpose_split<<<gT, 256>>>(wv, wThi + 2 * WSZ, wTlo + 2 * WSZ);
    transpose_split<<<gT, 256>>>(wo, wThi + 3 * WSZ, wTlo + 3 * WSZ);

    // Q/K/V projections (mma.sync)
    dim3 gG(D_MODEL / 128, MROWS / 128);
    gemm_mma<<<gG, 256, GEMM_SMEM>>>(xhi, xlo, wThi + 0 * WSZ, wTlo + 0 * WSZ, q,
                                     MROWS, D_MODEL, D_MODEL);
    gemm_mma<<<gG, 256, GEMM_SMEM>>>(xhi, xlo, wThi + 1 * WSZ, wTlo + 1 * WSZ, k,
                                     MROWS, D_MODEL, D_MODEL);
    gemm_mma<<<gG, 256, GEMM_SMEM>>>(xhi, xlo, wThi + 2 * WSZ, wTlo + 2 * WSZ, v,
                                     MROWS, D_MODEL, D_MODEL);

    rope_kernel<<<(MROWS * N_HEADS * 64) / 256, 256>>>(q, k);

    attn64<<<dim3(SEQ / BQ, BATCH * N_HEADS), 256, ATTN_SMEM>>>(q, k, v, a);

    // Output projection
    split_fp32<<<(MROWS * D_MODEL) / 256, 256>>>(a, ahi, alo);
    gemm_mma<<<gG, 256, GEMM_SMEM>>>(ahi, alo, wThi + 3 * WSZ, wTlo + 3 * WSZ, out,
                                     MROWS, D_MODEL, D_MODEL);
}

// round 11
// speedup vs baseline: 4.0371x; 2.4910x over previous
#include <cuda_runtime.h>
#include <cuda_bf16.h>
#include <math.h>
#include <stdint.h>

#define D_MODEL 2048
#define N_HEADS 16
#define HEAD_DIM 128
#define BATCH 2
#define SEQ 2048
#define MROWS (BATCH*SEQ)   /* 4096 */

// ---------------------------------------------------------------------------
// Scratch (static device globals: allocation-free per harness rules)
// ---------------------------------------------------------------------------
__device__ float g_q[(size_t)MROWS * D_MODEL];
__device__ float g_k[(size_t)MROWS * D_MODEL];
__device__ float g_v[(size_t)MROWS * D_MODEL];
__device__ int   g_pos[MROWS];

__device__ __nv_bfloat16 g_xhi[(size_t)MROWS * D_MODEL];
__device__ __nv_bfloat16 g_xlo[(size_t)MROWS * D_MODEL];
__device__ __nv_bfloat16 g_ahi[(size_t)MROWS * D_MODEL];
__device__ __nv_bfloat16 g_alo[(size_t)MROWS * D_MODEL];
__device__ __nv_bfloat16 g_wThi[4][(size_t)D_MODEL * D_MODEL];
__device__ __nv_bfloat16 g_wTlo[4][(size_t)D_MODEL * D_MODEL];
// head-major [(b*16+h)][s][d] bf16 hi/lo operands for attention
__device__ __nv_bfloat16 g_qhi[(size_t)MROWS * D_MODEL];
__device__ __nv_bfloat16 g_qlo[(size_t)MROWS * D_MODEL];
__device__ __nv_bfloat16 g_khi[(size_t)MROWS * D_MODEL];
__device__ __nv_bfloat16 g_klo[(size_t)MROWS * D_MODEL];
__device__ __nv_bfloat16 g_vhi[(size_t)MROWS * D_MODEL];
__device__ __nv_bfloat16 g_vlo[(size_t)MROWS * D_MODEL];

// ---------------------------------------------------------------------------
// Helpers (baseline PTX only: works on .target sm_103)
// ---------------------------------------------------------------------------
__device__ __forceinline__ uint32_t smem_to_u32(const void* p) {
    uint32_t a;
    asm("{ .reg .u64 t; cvta.to.shared.u64 t, %1; cvt.u32.u64 %0, t; }"
        : "=r"(a) : "l"(p));
    return a;
}
#define SMEM_SWIZZLE_128B(off) ((off) ^ (((off) >> 3) & 0x70))

__device__ __forceinline__ void ldsm_x4(uint32_t* r, uint32_t addr) {
    asm volatile("ldmatrix.sync.aligned.m8n8.x4.shared.b16 {%0,%1,%2,%3}, [%4];"
        : "=r"(r[0]), "=r"(r[1]), "=r"(r[2]), "=r"(r[3]) : "r"(addr));
}
__device__ __forceinline__ void ldsm_x4_t(uint32_t* r, uint32_t addr) {
    asm volatile("ldmatrix.sync.aligned.m8n8.x4.trans.shared.b16 {%0,%1,%2,%3}, [%4];"
        : "=r"(r[0]), "=r"(r[1]), "=r"(r[2]), "=r"(r[3]) : "r"(addr));
}
__device__ __forceinline__ void mma16816(float* c, const uint32_t* a, const uint32_t* b) {
    asm volatile("mma.sync.aligned.m16n8k16.row.col.f32.bf16.bf16.f32 "
        "{%0,%1,%2,%3}, {%4,%5,%6,%7}, {%8,%9}, {%0,%1,%2,%3};"
        : "+f"(c[0]), "+f"(c[1]), "+f"(c[2]), "+f"(c[3])
        : "r"(a[0]), "r"(a[1]), "r"(a[2]), "r"(a[3]), "r"(b[0]), "r"(b[1]));
}
#define CP_ASYNC16(sm, gp) \
    asm volatile("cp.async.cg.shared.global [%0], [%1], 16;" :: "r"(sm), "l"(gp))
#define CP_COMMIT() asm volatile("cp.async.commit_group;" ::: "memory")
#define CP_WAIT1()  asm volatile("cp.async.wait_group 1;" ::: "memory")
#define CP_WAIT0()  asm volatile("cp.async.wait_group 0;" ::: "memory")

// split two floats into packed bf16x2 hi and lo
__device__ __forceinline__ void split2(float x, float y, uint32_t& hi, uint32_t& lo) {
    __nv_bfloat162 h = __floats2bfloat162_rn(x, y);
    float hx = __bfloat162float(h.x);
    float hy = __bfloat162float(h.y);
    __nv_bfloat162 l = __floats2bfloat162_rn(x - hx, y - hy);
    hi = *(uint32_t*)&h;
    lo = *(uint32_t*)&l;
}

// ---------------------------------------------------------------------------
// Position normalization (int64-vs-int32 dtype detection)
// ---------------------------------------------------------------------------
__global__ __launch_bounds__(1024) void pos_norm_kernel(const int* __restrict__ raw)
{
    __shared__ int s_or[32];
    const int tid = threadIdx.x;
    int any = 0;
    for (int i = tid; i < 2048; i += 1024) any |= raw[2 * i + 1];
#pragma unroll
    for (int o = 16; o; o >>= 1) any |= __shfl_down_sync(0xFFFFFFFFu, any, o);
    if ((tid & 31) == 0) s_or[tid >> 5] = any;
    __syncthreads();
    if (tid < 32) {
        int v = s_or[tid];
#pragma unroll
        for (int o = 16; o; o >>= 1) v |= __shfl_down_sync(0xFFFFFFFFu, v, o);
        if (tid == 0) s_or[0] = v;
    }
    __syncthreads();
    const bool is64 = (s_or[0] == 0);
    for (int i = tid; i < MROWS; i += 1024)
        g_pos[i] = is64 ? raw[2 * i] : raw[i];
}

// ---------------------------------------------------------------------------
// fp32 -> (hi, lo) bf16 split, elementwise
// ---------------------------------------------------------------------------
__global__ __launch_bounds__(256) void split_fp32(const float* __restrict__ in,
                                                  __nv_bfloat16* __restrict__ hi,
                                                  __nv_bfloat16* __restrict__ lo)
{
    int i = blockIdx.x * 256 + threadIdx.x;
    float v = in[i];
    __nv_bfloat16 h = __float2bfloat16(v);
    hi[i] = h;
    lo[i] = __float2bfloat16(v - __bfloat162float(h));
}

// ---------------------------------------------------------------------------
// W[K][N] fp32 -> W^T[N][K] (hi, lo) bf16 split
// ---------------------------------------------------------------------------
__global__ __launch_bounds__(256) void transpose_split(const float* __restrict__ W,
                                                       __nv_bfloat16* __restrict__ hiT,
                                                       __nv_bfloat16* __restrict__ loT)
{
    __shared__ float t[32][33];
    const int n0 = blockIdx.x * 32, k0 = blockIdx.y * 32;
    const int tx = threadIdx.x & 31, ty = threadIdx.x >> 5;
#pragma unroll
    for (int r = ty; r < 32; r += 8)
        t[r][tx] = W[(size_t)(k0 + r) * D_MODEL + n0 + tx];
    __syncthreads();
#pragma unroll
    for (int r = ty; r < 32; r += 8) {
        float v = t[tx][r];
        __nv_bfloat16 h = __float2bfloat16(v);
        size_t o = (size_t)(n0 + r) * D_MODEL + k0 + tx;
        hiT[o] = h;
        loT[o] = __float2bfloat16(v - __bfloat162float(h));
    }
}

// ---------------------------------------------------------------------------
// mma.sync bf16 split GEMM (unchanged from R9, proven)
// ---------------------------------------------------------------------------
constexpr int GSTAGES = 3;
constexpr int GT_BYTES = 128 * 64 * 2;
constexpr int GSTAGE_BYTES = 4 * GT_BYTES;
constexpr int GEMM_SMEM = GSTAGES * GSTAGE_BYTES;

__device__ __forceinline__ void g_load_stage(uint32_t smst,
                                             const __nv_bfloat16* __restrict__ Ahi,
                                             const __nv_bfloat16* __restrict__ Alo,
                                             const __nv_bfloat16* __restrict__ Bhi,
                                             const __nv_bfloat16* __restrict__ Blo,
                                             int tileM, int tileN, int K, int kc, int tid)
{
    const __nv_bfloat16* gsrc[4];
    gsrc[0] = Ahi + (size_t)tileM * K + kc * 64;
    gsrc[1] = Alo + (size_t)tileM * K + kc * 64;
    gsrc[2] = Bhi + (size_t)tileN * K + kc * 64;
    gsrc[3] = Blo + (size_t)tileN * K + kc * 64;
    const size_t rs = (size_t)K * 2;
#pragma unroll
    for (int tsr = 0; tsr < 4; tsr++) {
        const char* gb = (const char*)gsrc[tsr];
        uint32_t sbase = smst + tsr * GT_BYTES;
#pragma unroll
        for (int it = 0; it < 4; it++) {
            int idx = it * 256 + tid;
            int r = idx >> 3, g = idx & 7;
            uint32_t so = sbase + SMEM_SWIZZLE_128B(r * 128 + g * 16);
            const char* gp = gb + (size_t)r * rs + g * 16;
            CP_ASYNC16(so, gp);
        }
    }
}

__global__ __launch_bounds__(256) void gemm_mma(const __nv_bfloat16* __restrict__ Ahi,
                                                const __nv_bfloat16* __restrict__ Alo,
                                                const __nv_bfloat16* __restrict__ Bhi,
                                                const __nv_bfloat16* __restrict__ Blo,
                                                float* __restrict__ C,
                                                int M, int N, int K)
{
    extern __shared__ char sm[];
    const uint32_t smb = smem_to_u32(sm);
    const int tid = threadIdx.x;
    const int wid = tid >> 5, lane = tid & 31;
    const int warp_m = wid & 1;
    const int warp_n = wid >> 1;
    const int tileN = blockIdx.x * 128, tileM = blockIdx.y * 128;

    float acc[4][4][4];
#pragma unroll
    for (int a = 0; a < 4; a++)
#pragma unroll
        for (int b = 0; b < 4; b++)
#pragma unroll
            for (int c = 0; c < 4; c++) acc[a][b][c] = 0.0f;

    const int niter = K / 64;

    g_load_stage(smb + 0 * GSTAGE_BYTES, Ahi, Alo, Bhi, Blo, tileM, tileN, K, 0, tid);
    CP_COMMIT();
    g_load_stage(smb + 1 * GSTAGE_BYTES, Ahi, Alo, Bhi, Blo, tileM, tileN, K, 1, tid);
    CP_COMMIT();

    const int a_r = (lane & 7) + ((lane >> 3) & 1) * 8;
    const int a_c = (lane >> 4) * 8;
    const int b_r = (lane & 7) + ((lane >> 4) & 1) * 8;
    const int b_c = ((lane >> 3) & 1) * 8;

    for (int i = 0; i < niter; i++) {
        CP_WAIT1();
        __syncthreads();

        if (i + 2 < niter)
            g_load_stage(smb + ((i + 2) % GSTAGES) * GSTAGE_BYTES,
                         Ahi, Alo, Bhi, Blo, tileM, tileN, K, i + 2, tid);
        CP_COMMIT();

        const uint32_t st = smb + (i % GSTAGES) * GSTAGE_BYTES;
        const uint32_t aHiB = st, aLoB = st + GT_BYTES;
        const uint32_t bHiB = st + 2 * GT_BYTES, bLoB = st + 3 * GT_BYTES;

#pragma unroll
        for (int ks = 0; ks < 4; ks++) {
            const int kb = ks * 16;
            uint32_t bh[4][2], bl[4][2];
#pragma unroll
            for (int np = 0; np < 2; np++) {
                const int n_base = warp_n * 32 + np * 16;
                uint32_t off = SMEM_SWIZZLE_128B((n_base + b_r) * 128 + (kb + b_c) * 2);
                uint32_t r4[4];
                ldsm_x4(r4, bHiB + off);
                bh[np * 2][0] = r4[0]; bh[np * 2][1] = r4[1];
                bh[np * 2 + 1][0] = r4[2]; bh[np * 2 + 1][1] = r4[3];
                ldsm_x4(r4, bLoB + off);
                bl[np * 2][0] = r4[0]; bl[np * 2][1] = r4[1];
                bl[np * 2 + 1][0] = r4[2]; bl[np * 2 + 1][1] = r4[3];
            }
#pragma unroll
            for (int mt = 0; mt < 4; mt++) {
                const int m_base = warp_m * 64 + mt * 16;
                uint32_t off = SMEM_SWIZZLE_128B((m_base + a_r) * 128 + (kb + a_c) * 2);
                uint32_t ah[4], al[4];
                ldsm_x4(ah, aHiB + off);
                ldsm_x4(al, aLoB + off);
#pragma unroll
                for (int nt = 0; nt < 4; nt++) {
                    mma16816(acc[mt][nt], ah, bh[nt]);
                    mma16816(acc[mt][nt], ah, bl[nt]);
                    mma16816(acc[mt][nt], al, bh[nt]);
                }
            }
        }
    }

    const int er = lane >> 2;
    const int ec = (lane & 3) * 2;
#pragma unroll
    for (int mt = 0; mt < 4; mt++) {
        const int row0 = tileM + warp_m * 64 + mt * 16 + er;
#pragma unroll
        for (int nt = 0; nt < 4; nt++) {
            const int col = tileN + warp_n * 32 + nt * 8 + ec;
            float* p0 = C + (size_t)row0 * N + col;
            float* p1 = C + (size_t)(row0 + 8) * N + col;
            *(float2*)p0 = make_float2(acc[mt][nt][0], acc[mt][nt][1]);
            *(float2*)p1 = make_float2(acc[mt][nt][2], acc[mt][nt][3]);
        }
    }
}

// ---------------------------------------------------------------------------
// Fused RoPE + bf16 split + head-major reorder for Q, K, V.
// Q additionally scaled by 1/sqrt(HEAD_DIM) (folded softmax scale).
// Output layout: [(b*16+h)][s][d], d contiguous.
// ---------------------------------------------------------------------------
__global__ __launch_bounds__(256) void qkv_convert()
{
    const float ASCALE = 0.08838834764831845f;
    int idx = blockIdx.x * 256 + threadIdx.x;  // MROWS*16*64 total
    int d  = idx & 63;
    int h  = (idx >> 6) & 15;
    int bs = idx >> 10;
    int b = bs >> 11, sidx = bs & (SEQ - 1);

    float invf = 1.0f / powf(10000.0f, (float)d * (1.0f / 64.0f));
    float angf = (float)g_pos[bs] * invf;
    double sa, ca;
    sincos((double)angf, &sa, &ca);
    float cc = (float)ca, ss = (float)sa;

    size_t src = (size_t)bs * D_MODEL + h * HEAD_DIM;
    size_t dst = ((size_t)(b * N_HEADS + h) * SEQ + sidx) * HEAD_DIM;

    float q1 = g_q[src + d], q2 = g_q[src + d + 64];
    float rq1 = (q1 * cc - q2 * ss) * ASCALE;
    float rq2 = (q2 * cc + q1 * ss) * ASCALE;
    __nv_bfloat16 hh;
    hh = __float2bfloat16(rq1); g_qhi[dst + d] = hh;
    g_qlo[dst + d] = __float2bfloat16(rq1 - __bfloat162float(hh));
    hh = __float2bfloat16(rq2); g_qhi[dst + d + 64] = hh;
    g_qlo[dst + d + 64] = __float2bfloat16(rq2 - __bfloat162float(hh));

    float k1 = g_k[src + d], k2 = g_k[src + d + 64];
    float rk1 = k1 * cc - k2 * ss;
    float rk2 = k2 * cc + k1 * ss;
    hh = __float2bfloat16(rk1); g_khi[dst + d] = hh;
    g_klo[dst + d] = __float2bfloat16(rk1 - __bfloat162float(hh));
    hh = __float2bfloat16(rk2); g_khi[dst + d + 64] = hh;
    g_klo[dst + d + 64] = __float2bfloat16(rk2 - __bfloat162float(hh));

    float v1 = g_v[src + d], v2 = g_v[src + d + 64];
    hh = __float2bfloat16(v1); g_vhi[dst + d] = hh;
    g_vlo[dst + d] = __float2bfloat16(v1 - __bfloat162float(hh));
    hh = __float2bfloat16(v2); g_vhi[dst + d + 64] = hh;
    g_vlo[dst + d + 64] = __float2bfloat16(v2 - __bfloat162float(hh));
}

// ---------------------------------------------------------------------------
// Tensor-core flash attention, split-bf16, causal tile skipping.
// CTA = (b,h) x 128-row q tile; 8 warps x 16 rows.
// smem: Qhi/Qlo + Khi/Klo + Vhi/Vlo, each 32KB (two 128x64 SW128 halves).
// Writes O directly as bf16 hi/lo split in [bs][D_MODEL] layout.
// ---------------------------------------------------------------------------
constexpr int AT_HB  = 16384;
constexpr int AT_TEN = 32768;
constexpr int ATQ = 0;
constexpr int ATK = 2 * AT_TEN;
constexpr int ATV = 4 * AT_TEN;
constexpr int ATTN_SMEM2 = 6 * AT_TEN;   // 196608

__device__ __forceinline__ void at_load_tile(uint32_t dst,
                                             const __nv_bfloat16* __restrict__ src,
                                             int tid)
{
    const char* gb = (const char*)src;
#pragma unroll
    for (int it = 0; it < 8; it++) {
        int ci = it * 256 + tid;
        int r = ci >> 4, g = ci & 15;
        uint32_t so = dst + (g >> 3) * AT_HB + SMEM_SWIZZLE_128B(r * 128 + (g & 7) * 16);
        CP_ASYNC16(so, gb + (size_t)r * 256 + g * 16);
    }
}

__global__ __launch_bounds__(256) void attn_mma(__nv_bfloat16* __restrict__ Ahi,
                                                __nv_bfloat16* __restrict__ Alo)
{
    extern __shared__ char sm[];
    const uint32_t smb = smem_to_u32(sm);
    const int tid = threadIdx.x, wid = tid >> 5, lane = tid & 31;
    const int qt = (int)(gridDim.x - 1) - (int)blockIdx.x;   // heavy tiles first
    const int bh = blockIdx.y;
    const int b = bh >> 4, h = bh & 15;
    const size_t hb = (size_t)bh * SEQ * HEAD_DIM;
    const int* posB = g_pos + b * SEQ;
    const int q0 = qt * 128;

    // Q tiles (hi/lo)
    at_load_tile(smb + ATQ, g_qhi + hb + (size_t)q0 * 128, tid);
    at_load_tile(smb + ATQ + AT_TEN, g_qlo + hb + (size_t)q0 * 128, tid);
    CP_COMMIT();

    // number of k-tiles: causal (qt+1) plus tie-overrun
    const int pqmax = __ldg(posB + q0 + 127);
    int nkt = qt + 1;
    for (int t2 = qt + 1; t2 < (int)gridDim.x; t2++) {
        if (__ldg(posB + t2 * 128) <= pqmax) nkt++; else break;
    }

    const int r0 = wid * 16 + (lane >> 2);
    const int pq0 = __ldg(posB + q0 + r0);
    const int pq1 = __ldg(posB + q0 + r0 + 8);

    float oacc[16][4];
#pragma unroll
    for (int i = 0; i < 16; i++)
#pragma unroll
        for (int j = 0; j < 4; j++) oacc[i][j] = 0.0f;
    float mA = -INFINITY, mB = -INFINITY, lA = 0.0f, lB = 0.0f;

    const int a_r = (lane & 7) + ((lane >> 3) & 1) * 8;
    const int a_c = (lane >> 4) * 8;
    const int b_r = (lane & 7) + ((lane >> 4) & 1) * 8;
    const int b_c = ((lane >> 3) & 1) * 8;
    // trans-V addressing (rows = seq, cols = d)
    const int t_r = (lane & 7) + ((lane >> 3) & 1) * 8;
    const int t_c = (lane >> 4) * 8;

    for (int kt = 0; kt < nkt; kt++) {
        __syncthreads();        // prior iteration done with K/V smem
        const size_t ko = hb + (size_t)kt * 128 * 128;
        at_load_tile(smb + ATK, g_khi + ko, tid);
        at_load_tile(smb + ATK + AT_TEN, g_klo + ko, tid);
        at_load_tile(smb + ATV, g_vhi + ko, tid);
        at_load_tile(smb + ATV + AT_TEN, g_vlo + ko, tid);
        CP_COMMIT();
        CP_WAIT0();
        __syncthreads();

        // ---- S = Q K^T (3-term split) ----
        float sS[16][4];
#pragma unroll
        for (int i = 0; i < 16; i++)
#pragma unroll
            for (int j = 0; j < 4; j++) sS[i][j] = 0.0f;

#pragma unroll
        for (int ks = 0; ks < 8; ks++) {
            const uint32_t halfoff = (ks >> 2) * AT_HB;
            const int kbh = (ks & 3) * 16;
            const uint32_t aoff = SMEM_SWIZZLE_128B((wid * 16 + a_r) * 128 + (kbh + a_c) * 2);
            uint32_t ah[4], al[4];
            ldsm_x4(ah, smb + ATQ + halfoff + aoff);
            ldsm_x4(al, smb + ATQ + AT_TEN + halfoff + aoff);
#pragma unroll
            for (int nb = 0; nb < 8; nb++) {
                const uint32_t boff = SMEM_SWIZZLE_128B((nb * 16 + b_r) * 128 + (kbh + b_c) * 2);
                uint32_t kh4[4], kl4[4];
                ldsm_x4(kh4, smb + ATK + halfoff + boff);
                ldsm_x4(kl4, smb + ATK + AT_TEN + halfoff + boff);
                mma16816(sS[nb * 2], ah, kh4);
                mma16816(sS[nb * 2], ah, kl4);
                mma16816(sS[nb * 2], al, kh4);
                mma16816(sS[nb * 2 + 1], ah, kh4 + 2);
                mma16816(sS[nb * 2 + 1], ah, kl4 + 2);
                mma16816(sS[nb * 2 + 1], al, kh4 + 2);
            }
        }

        // ---- mask (only tiles that can contain masked pairs) ----
        if (kt >= qt) {
            const int cb = kt * 128 + (lane & 3) * 2;
#pragma unroll
            for (int nt = 0; nt < 16; nt++) {
                int c0 = cb + nt * 8;
                int pk0 = __ldg(posB + c0), pk1 = __ldg(posB + c0 + 1);
                if (pq0 < pk0) sS[nt][0] = -1e30f;
                if (pq0 < pk1) sS[nt][1] = -1e30f;
                if (pq1 < pk0) sS[nt][2] = -1e30f;
                if (pq1 < pk1) sS[nt][3] = -1e30f;
            }
        }

        // ---- online softmax ----
        float mxA = -1e30f, mxB = -1e30f;
#pragma unroll
        for (int nt = 0; nt < 16; nt++) {
            mxA = fmaxf(mxA, fmaxf(sS[nt][0], sS[nt][1]));
            mxB = fmaxf(mxB, fmaxf(sS[nt][2], sS[nt][3]));
        }
        mxA = fmaxf(mxA, __shfl_xor_sync(0xFFFFFFFFu, mxA, 1));
        mxA = fmaxf(mxA, __shfl_xor_sync(0xFFFFFFFFu, mxA, 2));
        mxB = fmaxf(mxB, __shfl_xor_sync(0xFFFFFFFFu, mxB, 1));
        mxB = fmaxf(mxB, __shfl_xor_sync(0xFFFFFFFFu, mxB, 2));
        const float mnA = fmaxf(mA, mxA), mnB = fmaxf(mB, mxB);
        const float alA = __expf(mA - mnA), alB = __expf(mB - mnB);
        mA = mnA; mB = mnB;
        float smA = 0.0f, smB = 0.0f;
#pragma unroll
        for (int nt = 0; nt < 16; nt++) {
            sS[nt][0] = __expf(sS[nt][0] - mnA);
            sS[nt][1] = __expf(sS[nt][1] - mnA);
            sS[nt][2] = __expf(sS[nt][2] - mnB);
            sS[nt][3] = __expf(sS[nt][3] - mnB);
            smA += sS[nt][0] + sS[nt][1];
            smB += sS[nt][2] + sS[nt][3];
        }
        smA += __shfl_xor_sync(0xFFFFFFFFu, smA, 1);
        smA += __shfl_xor_sync(0xFFFFFFFFu, smA, 2);
        smB += __shfl_xor_sync(0xFFFFFFFFu, smB, 1);
        smB += __shfl_xor_sync(0xFFFFFFFFu, smB, 2);
        lA = lA * alA + smA;
        lB = lB * alB + smB;
#pragma unroll
        for (int nt = 0; nt < 16; nt++) {
            oacc[nt][0] *= alA; oacc[nt][1] *= alA;
            oacc[nt][2] *= alB; oacc[nt][3] *= alB;
        }

        // ---- O += P V (3-term split) ----
#pragma unroll
        for (int kv = 0; kv < 8; kv++) {
            uint32_t phi[4], plo[4];
            split2(sS[kv * 2][0], sS[kv * 2][1], phi[0], plo[0]);
            split2(sS[kv * 2][2], sS[kv * 2][3], phi[1], plo[1]);
            split2(sS[kv * 2 + 1][0], sS[kv * 2 + 1][1], phi[2], plo[2]);
            split2(sS[kv * 2 + 1][2], sS[kv * 2 + 1][3], phi[3], plo[3]);
#pragma unroll
            for (int dt = 0; dt < 8; dt++) {
                const int colb = dt * 16 + t_c;
                const uint32_t voff = (colb >> 6) * AT_HB +
                    SMEM_SWIZZLE_128B((kv * 16 + t_r) * 128 + (colb & 63) * 2);
                uint32_t vh4[4], vl4[4];
                ldsm_x4_t(vh4, smb + ATV + voff);
                ldsm_x4_t(vl4, smb + ATV + AT_TEN + voff);
                mma16816(oacc[dt * 2], phi, vh4);
                mma16816(oacc[dt * 2], phi, vl4);
                mma16816(oacc[dt * 2], plo, vh4);
                mma16816(oacc[dt * 2 + 1], phi, vh4 + 2);
                mma16816(oacc[dt * 2 + 1], phi, vl4 + 2);
                mma16816(oacc[dt * 2 + 1], plo, vh4 + 2);
            }
        }
    }

    // ---- epilogue: normalize, split to bf16 hi/lo, store [bs][D] ----
    const float liA = 1.0f / lA, liB = 1.0f / lB;
    const size_t rowA = (size_t)b * SEQ + q0 + r0;
    const size_t rowB = rowA + 8;
    const int cb = h * HEAD_DIM + (lane & 3) * 2;
#pragma unroll
    for (int nt = 0; nt < 16; nt++) {
        uint32_t hi01, lo01, hi23, lo23;
        split2(oacc[nt][0] * liA, oacc[nt][1] * liA, hi01, lo01);
        split2(oacc[nt][2] * liB, oacc[nt][3] * liB, hi23, lo23);
        const size_t oA = rowA * D_MODEL + cb + nt * 8;
        const size_t oB = rowB * D_MODEL + cb + nt * 8;
        *(uint32_t*)(Ahi + oA) = hi01;
        *(uint32_t*)(Alo + oA) = lo01;
        *(uint32_t*)(Ahi + oB) = hi23;
        *(uint32_t*)(Alo + oB) = lo23;
    }
}

// ---------------------------------------------------------------------------
extern "C" void kernel_launch(void* const* d_in, const int* in_sizes, int n_in,
                              void* d_out, int out_size)
{
    int idx_x = -1, idx_pos = -1;
    for (int i = 0; i < n_in; i++) {
        if (in_sizes[i] == MROWS * D_MODEL) idx_x = i;
        if (in_sizes[i] == MROWS)           idx_pos = i;
    }

    const float* x;
    const float *wq, *wk, *wv, *wo;
    const int* posraw;

    if (idx_x == 0) {   // dict order: x, Wq, Wk, Wv, Wo, pos
        x  = (const float*)d_in[0];
        wq = (const float*)d_in[1];
        wk = (const float*)d_in[2];
        wv = (const float*)d_in[3];
        wo = (const float*)d_in[4];
        posraw = (const int*)d_in[idx_pos >= 0 ? idx_pos : 5];
    } else {            // alphabetical: Wk, Wo, Wq, Wv, pos, x
        wk = (const float*)d_in[0];
        wo = (const float*)d_in[1];
        wq = (const float*)d_in[2];
        wv = (const float*)d_in[3];
        posraw = (const int*)d_in[idx_pos >= 0 ? idx_pos : 4];
        x  = (const float*)d_in[idx_x >= 0 ? idx_x : 5];
    }

    float* out = (float*)d_out;

    float *q, *k, *v;
    cudaGetSymbolAddress((void**)&q, g_q);
    cudaGetSymbolAddress((void**)&k, g_k);
    cudaGetSymbolAddress((void**)&v, g_v);
    __nv_bfloat16 *xhi, *xlo, *ahi, *alo, *wThi, *wTlo;
    cudaGetSymbolAddress((void**)&xhi, g_xhi);
    cudaGetSymbolAddress((void**)&xlo, g_xlo);
    cudaGetSymbolAddress((void**)&ahi, g_ahi);
    cudaGetSymbolAddress((void**)&alo, g_alo);
    cudaGetSymbolAddress((void**)&wThi, g_wThi);
    cudaGetSymbolAddress((void**)&wTlo, g_wTlo);
    const size_t WSZ = (size_t)D_MODEL * D_MODEL;

    cudaFuncSetAttribute(gemm_mma, cudaFuncAttributeMaxDynamicSharedMemorySize, GEMM_SMEM);
    cudaFuncSetAttribute(attn_mma, cudaFuncAttributeMaxDynamicSharedMemorySize, ATTN_SMEM2);

    pos_norm_kernel<<<1, 1024>>>(posraw);

    // Operand conversion
    split_fp32<<<(MROWS * D_MODEL) / 256, 256>>>(x, xhi, xlo);
    dim3 gT(D_MODEL / 32, D_MODEL / 32);
    transpose_split<<<gT, 256>>>(wq, wThi + 0 * WSZ, wTlo + 0 * WSZ);
    transpose_split<<<gT, 256>>>(wk, wThi + 1 * WSZ, wTlo + 1 * WSZ);
    transpose_split<<<gT, 256>>>(wv, wThi + 2 * WSZ, wTlo + 2 * WSZ);
    transpose_split<<<gT, 256>>>(wo, wThi + 3 * WSZ, wTlo + 3 * WSZ);

    // Q/K/V projections (mma.sync)
    dim3 gG(D_MODEL / 128, MROWS / 128);
    gemm_mma<<<gG, 256, GEMM_SMEM>>>(xhi, xlo, wThi + 0 * WSZ, wTlo + 0 * WSZ, q,
                                     MROWS, D_MODEL, D_MODEL);
    gemm_mma<<<gG, 256, GEMM_SMEM>>>(xhi, xlo, wThi + 1 * WSZ, wTlo + 1 * WSZ, k,
                                     MROWS, D_MODEL, D_MODEL);
    gemm_mma<<<gG, 256, GEMM_SMEM>>>(xhi, xlo, wThi + 2 * WSZ, wTlo + 2 * WSZ, v,
                                     MROWS, D_MODEL, D_MODEL);

    // RoPE + split + head-major reorder (fused)
    qkv_convert<<<(MROWS * N_HEADS * 64) / 256, 256>>>();

    // Tensor-core flash attention -> ahi/alo (bf16 split, [bs][D] layout)
    attn_mma<<<dim3(SEQ / 128, BATCH * N_HEADS), 256, ATTN_SMEM2>>>(ahi, alo);

    // Output projection
    gemm_mma<<<gG, 256, GEMM_SMEM>>>(ahi, alo, wThi + 3 * WSZ, wTlo + 3 * WSZ, out,
                                     MROWS, D_MODEL, D_MODEL);
}

// round 12
// speedup vs baseline: 4.7067x; 1.1659x over previous
#include <cuda_runtime.h>
#include <cuda_bf16.h>
#include <math.h>
#include <stdint.h>

#define D_MODEL 2048
#define N_HEADS 16
#define HEAD_DIM 128
#define BATCH 2
#define SEQ 2048
#define MROWS (BATCH*SEQ)   /* 4096 */

// ---------------------------------------------------------------------------
// Scratch (static device globals: allocation-free per harness rules)
// ---------------------------------------------------------------------------
__device__ float g_qkv[(size_t)MROWS * 3 * D_MODEL];   // fused QKV projection out
__device__ int   g_pos[MROWS];

__device__ __nv_bfloat16 g_xhi[(size_t)MROWS * D_MODEL];
__device__ __nv_bfloat16 g_xlo[(size_t)MROWS * D_MODEL];
__device__ __nv_bfloat16 g_ahi[(size_t)MROWS * D_MODEL];
__device__ __nv_bfloat16 g_alo[(size_t)MROWS * D_MODEL];
__device__ __nv_bfloat16 g_wThi[4][(size_t)D_MODEL * D_MODEL];
__device__ __nv_bfloat16 g_wTlo[4][(size_t)D_MODEL * D_MODEL];
// head-major [(b*16+h)][s][d] bf16 hi/lo operands for attention
__device__ __nv_bfloat16 g_qhi[(size_t)MROWS * D_MODEL];
__device__ __nv_bfloat16 g_qlo[(size_t)MROWS * D_MODEL];
__device__ __nv_bfloat16 g_khi[(size_t)MROWS * D_MODEL];
__device__ __nv_bfloat16 g_klo[(size_t)MROWS * D_MODEL];
__device__ __nv_bfloat16 g_vhi[(size_t)MROWS * D_MODEL];
__device__ __nv_bfloat16 g_vlo[(size_t)MROWS * D_MODEL];

// ---------------------------------------------------------------------------
// Helpers (baseline PTX only: works on .target sm_103)
// ---------------------------------------------------------------------------
__device__ __forceinline__ uint32_t smem_to_u32(const void* p) {
    uint32_t a;
    asm("{ .reg .u64 t; cvta.to.shared.u64 t, %1; cvt.u32.u64 %0, t; }"
        : "=r"(a) : "l"(p));
    return a;
}
#define SMEM_SWIZZLE_128B(off) ((off) ^ (((off) >> 3) & 0x70))

__device__ __forceinline__ void ldsm_x4(uint32_t* r, uint32_t addr) {
    asm volatile("ldmatrix.sync.aligned.m8n8.x4.shared.b16 {%0,%1,%2,%3}, [%4];"
        : "=r"(r[0]), "=r"(r[1]), "=r"(r[2]), "=r"(r[3]) : "r"(addr));
}
__device__ __forceinline__ void ldsm_x4_t(uint32_t* r, uint32_t addr) {
    asm volatile("ldmatrix.sync.aligned.m8n8.x4.trans.shared.b16 {%0,%1,%2,%3}, [%4];"
        : "=r"(r[0]), "=r"(r[1]), "=r"(r[2]), "=r"(r[3]) : "r"(addr));
}
__device__ __forceinline__ void mma16816(float* c, const uint32_t* a, const uint32_t* b) {
    asm volatile("mma.sync.aligned.m16n8k16.row.col.f32.bf16.bf16.f32 "
        "{%0,%1,%2,%3}, {%4,%5,%6,%7}, {%8,%9}, {%0,%1,%2,%3};"
        : "+f"(c[0]), "+f"(c[1]), "+f"(c[2]), "+f"(c[3])
        : "r"(a[0]), "r"(a[1]), "r"(a[2]), "r"(a[3]), "r"(b[0]), "r"(b[1]));
}
#define CP_ASYNC16(sm, gp) \
    asm volatile("cp.async.cg.shared.global [%0], [%1], 16;" :: "r"(sm), "l"(gp))
#define CP_COMMIT() asm volatile("cp.async.commit_group;" ::: "memory")
#define CP_WAIT1()  asm volatile("cp.async.wait_group 1;" ::: "memory")
#define CP_WAIT0()  asm volatile("cp.async.wait_group 0;" ::: "memory")

// split two floats into packed bf16x2 hi and lo
__device__ __forceinline__ void split2(float x, float y, uint32_t& hi, uint32_t& lo) {
    __nv_bfloat162 h = __floats2bfloat162_rn(x, y);
    float hx = __bfloat162float(h.x);
    float hy = __bfloat162float(h.y);
    __nv_bfloat162 l = __floats2bfloat162_rn(x - hx, y - hy);
    hi = *(uint32_t*)&h;
    lo = *(uint32_t*)&l;
}

// ---------------------------------------------------------------------------
// Position normalization (int64-vs-int32 dtype detection)
// ---------------------------------------------------------------------------
__global__ __launch_bounds__(1024) void pos_norm_kernel(const int* __restrict__ raw)
{
    __shared__ int s_or[32];
    const int tid = threadIdx.x;
    int any = 0;
    for (int i = tid; i < 2048; i += 1024) any |= raw[2 * i + 1];
#pragma unroll
    for (int o = 16; o; o >>= 1) any |= __shfl_down_sync(0xFFFFFFFFu, any, o);
    if ((tid & 31) == 0) s_or[tid >> 5] = any;
    __syncthreads();
    if (tid < 32) {
        int v = s_or[tid];
#pragma unroll
        for (int o = 16; o; o >>= 1) v |= __shfl_down_sync(0xFFFFFFFFu, v, o);
        if (tid == 0) s_or[0] = v;
    }
    __syncthreads();
    const bool is64 = (s_or[0] == 0);
    for (int i = tid; i < MROWS; i += 1024)
        g_pos[i] = is64 ? raw[2 * i] : raw[i];
}

// ---------------------------------------------------------------------------
// fp32 -> (hi, lo) bf16 split, elementwise
// ---------------------------------------------------------------------------
__global__ __launch_bounds__(256) void split_fp32(const float* __restrict__ in,
                                                  __nv_bfloat16* __restrict__ hi,
                                                  __nv_bfloat16* __restrict__ lo)
{
    int i = blockIdx.x * 256 + threadIdx.x;
    float v = in[i];
    __nv_bfloat16 h = __float2bfloat16(v);
    hi[i] = h;
    lo[i] = __float2bfloat16(v - __bfloat162float(h));
}

// ---------------------------------------------------------------------------
// W[K][N] fp32 -> W^T[N][K] (hi, lo) bf16 split
// ---------------------------------------------------------------------------
__global__ __launch_bounds__(256) void transpose_split(const float* __restrict__ W,
                                                       __nv_bfloat16* __restrict__ hiT,
                                                       __nv_bfloat16* __restrict__ loT)
{
    __shared__ float t[32][33];
    const int n0 = blockIdx.x * 32, k0 = blockIdx.y * 32;
    const int tx = threadIdx.x & 31, ty = threadIdx.x >> 5;
#pragma unroll
    for (int r = ty; r < 32; r += 8)
        t[r][tx] = W[(size_t)(k0 + r) * D_MODEL + n0 + tx];
    __syncthreads();
#pragma unroll
    for (int r = ty; r < 32; r += 8) {
        float v = t[tx][r];
        __nv_bfloat16 h = __float2bfloat16(v);
        size_t o = (size_t)(n0 + r) * D_MODEL + k0 + tx;
        hiT[o] = h;
        loT[o] = __float2bfloat16(v - __bfloat162float(h));
    }
}

// ---------------------------------------------------------------------------
// mma.sync bf16 split GEMM (proven R9 structure)
// ---------------------------------------------------------------------------
constexpr int GSTAGES = 3;
constexpr int GT_BYTES = 128 * 64 * 2;
constexpr int GSTAGE_BYTES = 4 * GT_BYTES;
constexpr int GEMM_SMEM = GSTAGES * GSTAGE_BYTES;

__device__ __forceinline__ void g_load_stage(uint32_t smst,
                                             const __nv_bfloat16* __restrict__ Ahi,
                                             const __nv_bfloat16* __restrict__ Alo,
                                             const __nv_bfloat16* __restrict__ Bhi,
                                             const __nv_bfloat16* __restrict__ Blo,
                                             int tileM, int tileN, int K, int kc, int tid)
{
    const __nv_bfloat16* gsrc[4];
    gsrc[0] = Ahi + (size_t)tileM * K + kc * 64;
    gsrc[1] = Alo + (size_t)tileM * K + kc * 64;
    gsrc[2] = Bhi + (size_t)tileN * K + kc * 64;
    gsrc[3] = Blo + (size_t)tileN * K + kc * 64;
    const size_t rs = (size_t)K * 2;
#pragma unroll
    for (int tsr = 0; tsr < 4; tsr++) {
        const char* gb = (const char*)gsrc[tsr];
        uint32_t sbase = smst + tsr * GT_BYTES;
#pragma unroll
        for (int it = 0; it < 4; it++) {
            int idx = it * 256 + tid;
            int r = idx >> 3, g = idx & 7;
            uint32_t so = sbase + SMEM_SWIZZLE_128B(r * 128 + g * 16);
            const char* gp = gb + (size_t)r * rs + g * 16;
            CP_ASYNC16(so, gp);
        }
    }
}

__global__ __launch_bounds__(256) void gemm_mma(const __nv_bfloat16* __restrict__ Ahi,
                                                const __nv_bfloat16* __restrict__ Alo,
                                                const __nv_bfloat16* __restrict__ Bhi,
                                                const __nv_bfloat16* __restrict__ Blo,
                                                float* __restrict__ C,
                                                int M, int N, int K)
{
    extern __shared__ char sm[];
    const uint32_t smb = smem_to_u32(sm);
    const int tid = threadIdx.x;
    const int wid = tid >> 5, lane = tid & 31;
    const int warp_m = wid & 1;
    const int warp_n = wid >> 1;
    const int tileN = blockIdx.x * 128, tileM = blockIdx.y * 128;

    float acc[4][4][4];
#pragma unroll
    for (int a = 0; a < 4; a++)
#pragma unroll
        for (int b = 0; b < 4; b++)
#pragma unroll
            for (int c = 0; c < 4; c++) acc[a][b][c] = 0.0f;

    const int niter = K / 64;

    g_load_stage(smb + 0 * GSTAGE_BYTES, Ahi, Alo, Bhi, Blo, tileM, tileN, K, 0, tid);
    CP_COMMIT();
    g_load_stage(smb + 1 * GSTAGE_BYTES, Ahi, Alo, Bhi, Blo, tileM, tileN, K, 1, tid);
    CP_COMMIT();

    const int a_r = (lane & 7) + ((lane >> 3) & 1) * 8;
    const int a_c = (lane >> 4) * 8;
    const int b_r = (lane & 7) + ((lane >> 4) & 1) * 8;
    const int b_c = ((lane >> 3) & 1) * 8;

    for (int i = 0; i < niter; i++) {
        CP_WAIT1();
        __syncthreads();

        if (i + 2 < niter)
            g_load_stage(smb + ((i + 2) % GSTAGES) * GSTAGE_BYTES,
                         Ahi, Alo, Bhi, Blo, tileM, tileN, K, i + 2, tid);
        CP_COMMIT();

        const uint32_t st = smb + (i % GSTAGES) * GSTAGE_BYTES;
        const uint32_t aHiB = st, aLoB = st + GT_BYTES;
        const uint32_t bHiB = st + 2 * GT_BYTES, bLoB = st + 3 * GT_BYTES;

#pragma unroll
        for (int ks = 0; ks < 4; ks++) {
            const int kb = ks * 16;
            uint32_t bh[4][2], bl[4][2];
#pragma unroll
            for (int np = 0; np < 2; np++) {
                const int n_base = warp_n * 32 + np * 16;
                uint32_t off = SMEM_SWIZZLE_128B((n_base + b_r) * 128 + (kb + b_c) * 2);
                uint32_t r4[4];
                ldsm_x4(r4, bHiB + off);
                bh[np * 2][0] = r4[0]; bh[np * 2][1] = r4[1];
                bh[np * 2 + 1][0] = r4[2]; bh[np * 2 + 1][1] = r4[3];
                ldsm_x4(r4, bLoB + off);
                bl[np * 2][0] = r4[0]; bl[np * 2][1] = r4[1];
                bl[np * 2 + 1][0] = r4[2]; bl[np * 2 + 1][1] = r4[3];
            }
#pragma unroll
            for (int mt = 0; mt < 4; mt++) {
                const int m_base = warp_m * 64 + mt * 16;
                uint32_t off = SMEM_SWIZZLE_128B((m_base + a_r) * 128 + (kb + a_c) * 2);
                uint32_t ah[4], al[4];
                ldsm_x4(ah, aHiB + off);
                ldsm_x4(al, aLoB + off);
#pragma unroll
                for (int nt = 0; nt < 4; nt++) {
                    mma16816(acc[mt][nt], ah, bh[nt]);
                    mma16816(acc[mt][nt], ah, bl[nt]);
                    mma16816(acc[mt][nt], al, bh[nt]);
                }
            }
        }
    }

    const int er = lane >> 2;
    const int ec = (lane & 3) * 2;
#pragma unroll
    for (int mt = 0; mt < 4; mt++) {
        const int row0 = tileM + warp_m * 64 + mt * 16 + er;
#pragma unroll
        for (int nt = 0; nt < 4; nt++) {
            const int col = tileN + warp_n * 32 + nt * 8 + ec;
            float* p0 = C + (size_t)row0 * N + col;
            float* p1 = C + (size_t)(row0 + 8) * N + col;
            *(float2*)p0 = make_float2(acc[mt][nt][0], acc[mt][nt][1]);
            *(float2*)p1 = make_float2(acc[mt][nt][2], acc[mt][nt][3]);
        }
    }
}

// ---------------------------------------------------------------------------
// Fused RoPE + bf16 split + head-major reorder, reading fused QKV buffer.
// Q additionally scaled by 1/sqrt(HEAD_DIM).
// ---------------------------------------------------------------------------
__global__ __launch_bounds__(256) void qkv_convert()
{
    const float ASCALE = 0.08838834764831845f;
    int idx = blockIdx.x * 256 + threadIdx.x;  // MROWS*16*64 total
    int d  = idx & 63;
    int h  = (idx >> 6) & 15;
    int bs = idx >> 10;
    int b = bs >> 11, sidx = bs & (SEQ - 1);

    float invf = 1.0f / powf(10000.0f, (float)d * (1.0f / 64.0f));
    float angf = (float)g_pos[bs] * invf;
    float ss, cc;
    sincosf(angf, &ss, &cc);

    size_t src = (size_t)bs * (3 * D_MODEL) + h * HEAD_DIM;
    size_t dst = ((size_t)(b * N_HEADS + h) * SEQ + sidx) * HEAD_DIM;

    float q1 = g_qkv[src + d], q2 = g_qkv[src + d + 64];
    float rq1 = (q1 * cc - q2 * ss) * ASCALE;
    float rq2 = (q2 * cc + q1 * ss) * ASCALE;
    __nv_bfloat16 hh;
    hh = __float2bfloat16(rq1); g_qhi[dst + d] = hh;
    g_qlo[dst + d] = __float2bfloat16(rq1 - __bfloat162float(hh));
    hh = __float2bfloat16(rq2); g_qhi[dst + d + 64] = hh;
    g_qlo[dst + d + 64] = __float2bfloat16(rq2 - __bfloat162float(hh));

    float k1 = g_qkv[src + D_MODEL + d], k2 = g_qkv[src + D_MODEL + d + 64];
    float rk1 = k1 * cc - k2 * ss;
    float rk2 = k2 * cc + k1 * ss;
    hh = __float2bfloat16(rk1); g_khi[dst + d] = hh;
    g_klo[dst + d] = __float2bfloat16(rk1 - __bfloat162float(hh));
    hh = __float2bfloat16(rk2); g_khi[dst + d + 64] = hh;
    g_klo[dst + d + 64] = __float2bfloat16(rk2 - __bfloat162float(hh));

    float v1 = g_qkv[src + 2 * D_MODEL + d], v2 = g_qkv[src + 2 * D_MODEL + d + 64];
    hh = __float2bfloat16(v1); g_vhi[dst + d] = hh;
    g_vlo[dst + d] = __float2bfloat16(v1 - __bfloat162float(hh));
    hh = __float2bfloat16(v2); g_vhi[dst + d + 64] = hh;
    g_vlo[dst + d + 64] = __float2bfloat16(v2 - __bfloat162float(hh));
}

// ---------------------------------------------------------------------------
// Tensor-core flash attention, split-bf16, causal tile skipping (R11 proven)
// ---------------------------------------------------------------------------
constexpr int AT_HB  = 16384;
constexpr int AT_TEN = 32768;
constexpr int ATQ = 0;
constexpr int ATK = 2 * AT_TEN;
constexpr int ATV = 4 * AT_TEN;
constexpr int ATTN_SMEM2 = 6 * AT_TEN;   // 196608

__device__ __forceinline__ void at_load_tile(uint32_t dst,
                                             const __nv_bfloat16* __restrict__ src,
                                             int tid)
{
    const char* gb = (const char*)src;
#pragma unroll
    for (int it = 0; it < 8; it++) {
        int ci = it * 256 + tid;
        int r = ci >> 4, g = ci & 15;
        uint32_t so = dst + (g >> 3) * AT_HB + SMEM_SWIZZLE_128B(r * 128 + (g & 7) * 16);
        CP_ASYNC16(so, gb + (size_t)r * 256 + g * 16);
    }
}

__global__ __launch_bounds__(256) void attn_mma(__nv_bfloat16* __restrict__ Ahi,
                                                __nv_bfloat16* __restrict__ Alo)
{
    extern __shared__ char sm[];
    const uint32_t smb = smem_to_u32(sm);
    const int tid = threadIdx.x, wid = tid >> 5, lane = tid & 31;
    const int qt = (int)(gridDim.x - 1) - (int)blockIdx.x;   // heavy tiles first
    const int bh = blockIdx.y;
    const int b = bh >> 4, h = bh & 15;
    const size_t hb = (size_t)bh * SEQ * HEAD_DIM;
    const int* posB = g_pos + b * SEQ;
    const int q0 = qt * 128;

    at_load_tile(smb + ATQ, g_qhi + hb + (size_t)q0 * 128, tid);
    at_load_tile(smb + ATQ + AT_TEN, g_qlo + hb + (size_t)q0 * 128, tid);
    CP_COMMIT();

    const int pqmax = __ldg(posB + q0 + 127);
    int nkt = qt + 1;
    for (int t2 = qt + 1; t2 < (int)gridDim.x; t2++) {
        if (__ldg(posB + t2 * 128) <= pqmax) nkt++; else break;
    }

    const int r0 = wid * 16 + (lane >> 2);
    const int pq0 = __ldg(posB + q0 + r0);
    const int pq1 = __ldg(posB + q0 + r0 + 8);

    float oacc[16][4];
#pragma unroll
    for (int i = 0; i < 16; i++)
#pragma unroll
        for (int j = 0; j < 4; j++) oacc[i][j] = 0.0f;
    float mA = -INFINITY, mB = -INFINITY, lA = 0.0f, lB = 0.0f;

    const int a_r = (lane & 7) + ((lane >> 3) & 1) * 8;
    const int a_c = (lane >> 4) * 8;
    const int b_r = (lane & 7) + ((lane >> 4) & 1) * 8;
    const int b_c = ((lane >> 3) & 1) * 8;
    const int t_r = (lane & 7) + ((lane >> 3) & 1) * 8;
    const int t_c = (lane >> 4) * 8;

    for (int kt = 0; kt < nkt; kt++) {
        __syncthreads();
        const size_t ko = hb + (size_t)kt * 128 * 128;
        at_load_tile(smb + ATK, g_khi + ko, tid);
        at_load_tile(smb + ATK + AT_TEN, g_klo + ko, tid);
        at_load_tile(smb + ATV, g_vhi + ko, tid);
        at_load_tile(smb + ATV + AT_TEN, g_vlo + ko, tid);
        CP_COMMIT();
        CP_WAIT0();
        __syncthreads();

        // ---- S = Q K^T (3-term split) ----
        float sS[16][4];
#pragma unroll
        for (int i = 0; i < 16; i++)
#pragma unroll
            for (int j = 0; j < 4; j++) sS[i][j] = 0.0f;

#pragma unroll
        for (int ks = 0; ks < 8; ks++) {
            const uint32_t halfoff = (ks >> 2) * AT_HB;
            const int kbh = (ks & 3) * 16;
            const uint32_t aoff = SMEM_SWIZZLE_128B((wid * 16 + a_r) * 128 + (kbh + a_c) * 2);
            uint32_t ah[4], al[4];
            ldsm_x4(ah, smb + ATQ + halfoff + aoff);
            ldsm_x4(al, smb + ATQ + AT_TEN + halfoff + aoff);
#pragma unroll
            for (int nb = 0; nb < 8; nb++) {
                const uint32_t boff = SMEM_SWIZZLE_128B((nb * 16 + b_r) * 128 + (kbh + b_c) * 2);
                uint32_t kh4[4], kl4[4];
                ldsm_x4(kh4, smb + ATK + halfoff + boff);
                ldsm_x4(kl4, smb + ATK + AT_TEN + halfoff + boff);
                mma16816(sS[nb * 2], ah, kh4);
                mma16816(sS[nb * 2], ah, kl4);
                mma16816(sS[nb * 2], al, kh4);
                mma16816(sS[nb * 2 + 1], ah, kh4 + 2);
                mma16816(sS[nb * 2 + 1], ah, kl4 + 2);
                mma16816(sS[nb * 2 + 1], al, kh4 + 2);
            }
        }

        // ---- mask ----
        if (kt >= qt) {
            const int cb = kt * 128 + (lane & 3) * 2;
#pragma unroll
            for (int nt = 0; nt < 16; nt++) {
                int c0 = cb + nt * 8;
                int pk0 = __ldg(posB + c0), pk1 = __ldg(posB + c0 + 1);
                if (pq0 < pk0) sS[nt][0] = -1e30f;
                if (pq0 < pk1) sS[nt][1] = -1e30f;
                if (pq1 < pk0) sS[nt][2] = -1e30f;
                if (pq1 < pk1) sS[nt][3] = -1e30f;
            }
        }

        // ---- online softmax ----
        float mxA = -1e30f, mxB = -1e30f;
#pragma unroll
        for (int nt = 0; nt < 16; nt++) {
            mxA = fmaxf(mxA, fmaxf(sS[nt][0], sS[nt][1]));
            mxB = fmaxf(mxB, fmaxf(sS[nt][2], sS[nt][3]));
        }
        mxA = fmaxf(mxA, __shfl_xor_sync(0xFFFFFFFFu, mxA, 1));
        mxA = fmaxf(mxA, __shfl_xor_sync(0xFFFFFFFFu, mxA, 2));
        mxB = fmaxf(mxB, __shfl_xor_sync(0xFFFFFFFFu, mxB, 1));
        mxB = fmaxf(mxB, __shfl_xor_sync(0xFFFFFFFFu, mxB, 2));
        const float mnA = fmaxf(mA, mxA), mnB = fmaxf(mB, mxB);
        const float alA = __expf(mA - mnA), alB = __expf(mB - mnB);
        mA = mnA; mB = mnB;
        float smA = 0.0f, smB = 0.0f;
#pragma unroll
        for (int nt = 0; nt < 16; nt++) {
            sS[nt][0] = __expf(sS[nt][0] - mnA);
            sS[nt][1] = __expf(sS[nt][1] - mnA);
            sS[nt][2] = __expf(sS[nt][2] - mnB);
            sS[nt][3] = __expf(sS[nt][3] - mnB);
            smA += sS[nt][0] + sS[nt][1];
            smB += sS[nt][2] + sS[nt][3];
        }
        smA += __shfl_xor_sync(0xFFFFFFFFu, smA, 1);
        smA += __shfl_xor_sync(0xFFFFFFFFu, smA, 2);
        smB += __shfl_xor_sync(0xFFFFFFFFu, smB, 1);
        smB += __shfl_xor_sync(0xFFFFFFFFu, smB, 2);
        lA = lA * alA + smA;
        lB = lB * alB + smB;
#pragma unroll
        for (int nt = 0; nt < 16; nt++) {
            oacc[nt][0] *= alA; oacc[nt][1] *= alA;
            oacc[nt][2] *= alB; oacc[nt][3] *= alB;
        }

        // ---- O += P V (3-term split) ----
#pragma unroll
        for (int kv = 0; kv < 8; kv++) {
            uint32_t phi[4], plo[4];
            split2(sS[kv * 2][0], sS[kv * 2][1], phi[0], plo[0]);
            split2(sS[kv * 2][2], sS[kv * 2][3], phi[1], plo[1]);
            split2(sS[kv * 2 + 1][0], sS[kv * 2 + 1][1], phi[2], plo[2]);
            split2(sS[kv * 2 + 1][2], sS[kv * 2 + 1][3], phi[3], plo[3]);
#pragma unroll
            for (int dt = 0; dt < 8; dt++) {
                const int colb = dt * 16 + t_c;
                const uint32_t voff = (colb >> 6) * AT_HB +
                    SMEM_SWIZZLE_128B((kv * 16 + t_r) * 128 + (colb & 63) * 2);
                uint32_t vh4[4], vl4[4];
                ldsm_x4_t(vh4, smb + ATV + voff);
                ldsm_x4_t(vl4, smb + ATV + AT_TEN + voff);
                mma16816(oacc[dt * 2], phi, vh4);
                mma16816(oacc[dt * 2], phi, vl4);
                mma16816(oacc[dt * 2], plo, vh4);
                mma16816(oacc[dt * 2 + 1], phi, vh4 + 2);
                mma16816(oacc[dt * 2 + 1], phi, vl4 + 2);
                mma16816(oacc[dt * 2 + 1], plo, vh4 + 2);
            }
        }
    }

    // ---- epilogue ----
    const float liA = 1.0f / lA, liB = 1.0f / lB;
    const size_t rowA = (size_t)b * SEQ + q0 + r0;
    const size_t rowB = rowA + 8;
    const int cb = h * HEAD_DIM + (lane & 3) * 2;
#pragma unroll
    for (int nt = 0; nt < 16; nt++) {
        uint32_t hi01, lo01, hi23, lo23;
        split2(oacc[nt][0] * liA, oacc[nt][1] * liA, hi01, lo01);
        split2(oacc[nt][2] * liB, oacc[nt][3] * liB, hi23, lo23);
        const size_t oA = rowA * D_MODEL + cb + nt * 8;
        const size_t oB = rowB * D_MODEL + cb + nt * 8;
        *(uint32_t*)(Ahi + oA) = hi01;
        *(uint32_t*)(Alo + oA) = lo01;
        *(uint32_t*)(Ahi + oB) = hi23;
        *(uint32_t*)(Alo + oB) = lo23;
    }
}

// ---------------------------------------------------------------------------
extern "C" void kernel_launch(void* const* d_in, const int* in_sizes, int n_in,
                              void* d_out, int out_size)
{
    int idx_x = -1, idx_pos = -1;
    for (int i = 0; i < n_in; i++) {
        if (in_sizes[i] == MROWS * D_MODEL) idx_x = i;
        if (in_sizes[i] == MROWS)           idx_pos = i;
    }

    const float* x;
    const float *wq, *wk, *wv, *wo;
    const int* posraw;

    if (idx_x == 0) {   // dict order: x, Wq, Wk, Wv, Wo, pos
        x  = (const float*)d_in[0];
        wq = (const float*)d_in[1];
        wk = (const float*)d_in[2];
        wv = (const float*)d_in[3];
        wo = (const float*)d_in[4];
        posraw = (const int*)d_in[idx_pos >= 0 ? idx_pos : 5];
    } else {            // alphabetical: Wk, Wo, Wq, Wv, pos, x
        wk = (const float*)d_in[0];
        wo = (const float*)d_in[1];
        wq = (const float*)d_in[2];
        wv = (const float*)d_in[3];
        posraw = (const int*)d_in[idx_pos >= 0 ? idx_pos : 4];
        x  = (const float*)d_in[idx_x >= 0 ? idx_x : 5];
    }

    float* out = (float*)d_out;

    float* qkv;
    cudaGetSymbolAddress((void**)&qkv, g_qkv);
    __nv_bfloat16 *xhi, *xlo, *ahi, *alo, *wThi, *wTlo;
    cudaGetSymbolAddress((void**)&xhi, g_xhi);
    cudaGetSymbolAddress((void**)&xlo, g_xlo);
    cudaGetSymbolAddress((void**)&ahi, g_ahi);
    cudaGetSymbolAddress((void**)&alo, g_alo);
    cudaGetSymbolAddress((void**)&wThi, g_wThi);
    cudaGetSymbolAddress((void**)&wTlo, g_wTlo);
    const size_t WSZ = (size_t)D_MODEL * D_MODEL;

    cudaFuncSetAttribute(gemm_mma, cudaFuncAttributeMaxDynamicSharedMemorySize, GEMM_SMEM);
    cudaFuncSetAttribute(attn_mma, cudaFuncAttributeMaxDynamicSharedMemorySize, ATTN_SMEM2);

    // Launch order arranged so the 6th launch (ncu -s 5 -c 1) is the fused
    // QKV gemm_mma — the hot kernel we need the profile of.
    split_fp32<<<(MROWS * D_MODEL) / 256, 256>>>(x, xhi, xlo);          // 1
    dim3 gT(D_MODEL / 32, D_MODEL / 32);
    transpose_split<<<gT, 256>>>(wq, wThi + 0 * WSZ, wTlo + 0 * WSZ);   // 2
    transpose_split<<<gT, 256>>>(wk, wThi + 1 * WSZ, wTlo + 1 * WSZ);   // 3
    transpose_split<<<gT, 256>>>(wv, wThi + 2 * WSZ, wTlo + 2 * WSZ);   // 4
    transpose_split<<<gT, 256>>>(wo, wThi + 3 * WSZ, wTlo + 3 * WSZ);   // 5

    // Fused Q/K/V projection: N = 3*D_MODEL (weights contiguous)          6
    dim3 gQKV(3 * D_MODEL / 128, MROWS / 128);
    gemm_mma<<<gQKV, 256, GEMM_SMEM>>>(xhi, xlo, wThi, wTlo, qkv,
                                       MROWS, 3 * D_MODEL, D_MODEL);

    pos_norm_kernel<<<1, 1024>>>(posraw);                               // 7

    // RoPE + split + head-major reorder (fused)                           8
    qkv_convert<<<(MROWS * N_HEADS * 64) / 256, 256>>>();

    // Tensor-core flash attention -> ahi/alo                              9
    attn_mma<<<dim3(SEQ / 128, BATCH * N_HEADS), 256, ATTN_SMEM2>>>(ahi, alo);

    // Output projection                                                   10
    dim3 gG(D_MODEL / 128, MROWS / 128);
    gemm_mma<<<gG, 256, GEMM_SMEM>>>(ahi, alo, wThi + 3 * WSZ, wTlo + 3 * WSZ, out,
                                     MROWS, D_MODEL, D_MODEL);
}

// round 16
// speedup vs baseline: 4.7379x; 1.0066x over previous
#include <cuda_runtime.h>
#include <cuda_bf16.h>
#include <math.h>
#include <stdint.h>

#define D_MODEL 2048
#define N_HEADS 16
#define HEAD_DIM 128
#define BATCH 2
#define SEQ 2048
#define MROWS (BATCH*SEQ)   /* 4096 */

// ---------------------------------------------------------------------------
// Scratch (static device globals: allocation-free per harness rules)
// ---------------------------------------------------------------------------
__device__ float g_qkv[(size_t)MROWS * 3 * D_MODEL];   // fused QKV projection out
__device__ int   g_pos[MROWS];

__device__ __nv_bfloat16 g_xhi[(size_t)MROWS * D_MODEL];
__device__ __nv_bfloat16 g_xlo[(size_t)MROWS * D_MODEL];
__device__ __nv_bfloat16 g_ahi[(size_t)MROWS * D_MODEL];
__device__ __nv_bfloat16 g_alo[(size_t)MROWS * D_MODEL];
__device__ __nv_bfloat16 g_wThi[4][(size_t)D_MODEL * D_MODEL];
__device__ __nv_bfloat16 g_wTlo[4][(size_t)D_MODEL * D_MODEL];
// head-major [(b*16+h)][s][d] bf16 hi/lo operands for attention
__device__ __nv_bfloat16 g_qhi[(size_t)MROWS * D_MODEL];
__device__ __nv_bfloat16 g_qlo[(size_t)MROWS * D_MODEL];
__device__ __nv_bfloat16 g_khi[(size_t)MROWS * D_MODEL];
__device__ __nv_bfloat16 g_klo[(size_t)MROWS * D_MODEL];
__device__ __nv_bfloat16 g_vhi[(size_t)MROWS * D_MODEL];
__device__ __nv_bfloat16 g_vlo[(size_t)MROWS * D_MODEL];

// ---------------------------------------------------------------------------
// Helpers (baseline PTX only: works on .target sm_103)
// ---------------------------------------------------------------------------
__device__ __forceinline__ uint32_t smem_to_u32(const void* p) {
    uint32_t a;
    asm("{ .reg .u64 t; cvta.to.shared.u64 t, %1; cvt.u32.u64 %0, t; }"
        : "=r"(a) : "l"(p));
    return a;
}
#define SMEM_SWIZZLE_128B(off) ((off) ^ (((off) >> 3) & 0x70))

__device__ __forceinline__ void ldsm_x4(uint32_t* r, uint32_t addr) {
    asm volatile("ldmatrix.sync.aligned.m8n8.x4.shared.b16 {%0,%1,%2,%3}, [%4];"
        : "=r"(r[0]), "=r"(r[1]), "=r"(r[2]), "=r"(r[3]) : "r"(addr));
}
__device__ __forceinline__ void ldsm_x4_t(uint32_t* r, uint32_t addr) {
    asm volatile("ldmatrix.sync.aligned.m8n8.x4.trans.shared.b16 {%0,%1,%2,%3}, [%4];"
        : "=r"(r[0]), "=r"(r[1]), "=r"(r[2]), "=r"(r[3]) : "r"(addr));
}
__device__ __forceinline__ void mma16816(float* c, const uint32_t* a, const uint32_t* b) {
    asm volatile("mma.sync.aligned.m16n8k16.row.col.f32.bf16.bf16.f32 "
        "{%0,%1,%2,%3}, {%4,%5,%6,%7}, {%8,%9}, {%0,%1,%2,%3};"
        : "+f"(c[0]), "+f"(c[1]), "+f"(c[2]), "+f"(c[3])
        : "r"(a[0]), "r"(a[1]), "r"(a[2]), "r"(a[3]), "r"(b[0]), "r"(b[1]));
}
#define CP_ASYNC16(sm, gp) \
    asm volatile("cp.async.cg.shared.global [%0], [%1], 16;" :: "r"(sm), "l"(gp))
#define CP_COMMIT() asm volatile("cp.async.commit_group;" ::: "memory")
#define CP_WAIT1()  asm volatile("cp.async.wait_group 1;" ::: "memory")
#define CP_WAIT0()  asm volatile("cp.async.wait_group 0;" ::: "memory")

// split two floats into packed bf16x2 hi and lo
__device__ __forceinline__ void split2(float x, float y, uint32_t& hi, uint32_t& lo) {
    __nv_bfloat162 h = __floats2bfloat162_rn(x, y);
    float hx = __bfloat162float(h.x);
    float hy = __bfloat162float(h.y);
    __nv_bfloat162 l = __floats2bfloat162_rn(x - hx, y - hy);
    hi = *(uint32_t*)&h;
    lo = *(uint32_t*)&l;
}

// ---------------------------------------------------------------------------
// Position normalization (int64-vs-int32 dtype detection)
// ---------------------------------------------------------------------------
__global__ __launch_bounds__(1024) void pos_norm_kernel(const int* __restrict__ raw)
{
    __shared__ int s_or[32];
    const int tid = threadIdx.x;
    int any = 0;
    for (int i = tid; i < 2048; i += 1024) any |= raw[2 * i + 1];
#pragma unroll
    for (int o = 16; o; o >>= 1) any |= __shfl_down_sync(0xFFFFFFFFu, any, o);
    if ((tid & 31) == 0) s_or[tid >> 5] = any;
    __syncthreads();
    if (tid < 32) {
        int v = s_or[tid];
#pragma unroll
        for (int o = 16; o; o >>= 1) v |= __shfl_down_sync(0xFFFFFFFFu, v, o);
        if (tid == 0) s_or[0] = v;
    }
    __syncthreads();
    const bool is64 = (s_or[0] == 0);
    for (int i = tid; i < MROWS; i += 1024)
        g_pos[i] = is64 ? raw[2 * i] : raw[i];
}

// ---------------------------------------------------------------------------
// fp32 -> (hi, lo) bf16 split, elementwise
// ---------------------------------------------------------------------------
__global__ __launch_bounds__(256) void split_fp32(const float* __restrict__ in,
                                                  __nv_bfloat16* __restrict__ hi,
                                                  __nv_bfloat16* __restrict__ lo)
{
    int i = blockIdx.x * 256 + threadIdx.x;
    float v = in[i];
    __nv_bfloat16 h = __float2bfloat16(v);
    hi[i] = h;
    lo[i] = __float2bfloat16(v - __bfloat162float(h));
}

// ---------------------------------------------------------------------------
// All four W[K][N] fp32 -> W^T[N][K] (hi, lo) bf16 splits in one launch
// (gridDim.z selects the weight matrix).
// ---------------------------------------------------------------------------
__global__ __launch_bounds__(256) void transpose_split4(const float* __restrict__ w0,
                                                        const float* __restrict__ w1,
                                                        const float* __restrict__ w2,
                                                        const float* __restrict__ w3,
                                                        __nv_bfloat16* __restrict__ hiT,
                                                        __nv_bfloat16* __restrict__ loT)
{
    __shared__ float t[32][33];
    const int z = blockIdx.z;
    const float* W = (z == 0) ? w0 : (z == 1) ? w1 : (z == 2) ? w2 : w3;
    const size_t WSZ = (size_t)D_MODEL * D_MODEL;
    __nv_bfloat16* hi = hiT + z * WSZ;
    __nv_bfloat16* lo = loT + z * WSZ;

    const int n0 = blockIdx.x * 32, k0 = blockIdx.y * 32;
    const int tx = threadIdx.x & 31, ty = threadIdx.x >> 5;
#pragma unroll
    for (int r = ty; r < 32; r += 8)
        t[r][tx] = W[(size_t)(k0 + r) * D_MODEL + n0 + tx];
    __syncthreads();
#pragma unroll
    for (int r = ty; r < 32; r += 8) {
        float v = t[tx][r];
        __nv_bfloat16 h = __float2bfloat16(v);
        size_t o = (size_t)(n0 + r) * D_MODEL + k0 + tx;
        hi[o] = h;
        lo[o] = __float2bfloat16(v - __bfloat162float(h));
    }
}

// ---------------------------------------------------------------------------
// mma.sync bf16 split GEMM (proven R9 structure)
// ---------------------------------------------------------------------------
constexpr int GSTAGES = 3;
constexpr int GT_BYTES = 128 * 64 * 2;
constexpr int GSTAGE_BYTES = 4 * GT_BYTES;
constexpr int GEMM_SMEM = GSTAGES * GSTAGE_BYTES;

__device__ __forceinline__ void g_load_stage(uint32_t smst,
                                             const __nv_bfloat16* __restrict__ Ahi,
                                             const __nv_bfloat16* __restrict__ Alo,
                                             const __nv_bfloat16* __restrict__ Bhi,
                                             const __nv_bfloat16* __restrict__ Blo,
                                             int tileM, int tileN, int K, int kc, int tid)
{
    const __nv_bfloat16* gsrc[4];
    gsrc[0] = Ahi + (size_t)tileM * K + kc * 64;
    gsrc[1] = Alo + (size_t)tileM * K + kc * 64;
    gsrc[2] = Bhi + (size_t)tileN * K + kc * 64;
    gsrc[3] = Blo + (size_t)tileN * K + kc * 64;
    const size_t rs = (size_t)K * 2;
#pragma unroll
    for (int tsr = 0; tsr < 4; tsr++) {
        const char* gb = (const char*)gsrc[tsr];
        uint32_t sbase = smst + tsr * GT_BYTES;
#pragma unroll
        for (int it = 0; it < 4; it++) {
            int idx = it * 256 + tid;
            int r = idx >> 3, g = idx & 7;
            uint32_t so = sbase + SMEM_SWIZZLE_128B(r * 128 + g * 16);
            const char* gp = gb + (size_t)r * rs + g * 16;
            CP_ASYNC16(so, gp);
        }
    }
}

__global__ __launch_bounds__(256) void gemm_mma(const __nv_bfloat16* __restrict__ Ahi,
                                                const __nv_bfloat16* __restrict__ Alo,
                                                const __nv_bfloat16* __restrict__ Bhi,
                                                const __nv_bfloat16* __restrict__ Blo,
                                                float* __restrict__ C,
                                                int M, int N, int K)
{
    extern __shared__ char sm[];
    const uint32_t smb = smem_to_u32(sm);
    const int tid = threadIdx.x;
    const int wid = tid >> 5, lane = tid & 31;
    const int warp_m = wid & 1;
    const int warp_n = wid >> 1;
    const int tileN = blockIdx.x * 128, tileM = blockIdx.y * 128;

    float acc[4][4][4];
#pragma unroll
    for (int a = 0; a < 4; a++)
#pragma unroll
        for (int b = 0; b < 4; b++)
#pragma unroll
            for (int c = 0; c < 4; c++) acc[a][b][c] = 0.0f;

    const int niter = K / 64;

    g_load_stage(smb + 0 * GSTAGE_BYTES, Ahi, Alo, Bhi, Blo, tileM, tileN, K, 0, tid);
    CP_COMMIT();
    g_load_stage(smb + 1 * GSTAGE_BYTES, Ahi, Alo, Bhi, Blo, tileM, tileN, K, 1, tid);
    CP_COMMIT();

    const int a_r = (lane & 7) + ((lane >> 3) & 1) * 8;
    const int a_c = (lane >> 4) * 8;
    const int b_r = (lane & 7) + ((lane >> 4) & 1) * 8;
    const int b_c = ((lane >> 3) & 1) * 8;

    for (int i = 0; i < niter; i++) {
        CP_WAIT1();
        __syncthreads();

        if (i + 2 < niter)
            g_load_stage(smb + ((i + 2) % GSTAGES) * GSTAGE_BYTES,
                         Ahi, Alo, Bhi, Blo, tileM, tileN, K, i + 2, tid);
        CP_COMMIT();

        const uint32_t st = smb + (i % GSTAGES) * GSTAGE_BYTES;
        const uint32_t aHiB = st, aLoB = st + GT_BYTES;
        const uint32_t bHiB = st + 2 * GT_BYTES, bLoB = st + 3 * GT_BYTES;

#pragma unroll
        for (int ks = 0; ks < 4; ks++) {
            const int kb = ks * 16;
            uint32_t bh[4][2], bl[4][2];
#pragma unroll
            for (int np = 0; np < 2; np++) {
                const int n_base = warp_n * 32 + np * 16;
                uint32_t off = SMEM_SWIZZLE_128B((n_base + b_r) * 128 + (kb + b_c) * 2);
                uint32_t r4[4];
                ldsm_x4(r4, bHiB + off);
                bh[np * 2][0] = r4[0]; bh[np * 2][1] = r4[1];
                bh[np * 2 + 1][0] = r4[2]; bh[np * 2 + 1][1] = r4[3];
                ldsm_x4(r4, bLoB + off);
                bl[np * 2][0] = r4[0]; bl[np * 2][1] = r4[1];
                bl[np * 2 + 1][0] = r4[2]; bl[np * 2 + 1][1] = r4[3];
            }
#pragma unroll
            for (int mt = 0; mt < 4; mt++) {
                const int m_base = warp_m * 64 + mt * 16;
                uint32_t off = SMEM_SWIZZLE_128B((m_base + a_r) * 128 + (kb + a_c) * 2);
                uint32_t ah[4], al[4];
                ldsm_x4(ah, aHiB + off);
                ldsm_x4(al, aLoB + off);
#pragma unroll
                for (int nt = 0; nt < 4; nt++) {
                    mma16816(acc[mt][nt], ah, bh[nt]);
                    mma16816(acc[mt][nt], ah, bl[nt]);
                    mma16816(acc[mt][nt], al, bh[nt]);
                }
            }
        }
    }

    const int er = lane >> 2;
    const int ec = (lane & 3) * 2;
#pragma unroll
    for (int mt = 0; mt < 4; mt++) {
        const int row0 = tileM + warp_m * 64 + mt * 16 + er;
#pragma unroll
        for (int nt = 0; nt < 4; nt++) {
            const int col = tileN + warp_n * 32 + nt * 8 + ec;
            float* p0 = C + (size_t)row0 * N + col;
            float* p1 = C + (size_t)(row0 + 8) * N + col;
            *(float2*)p0 = make_float2(acc[mt][nt][0], acc[mt][nt][1]);
            *(float2*)p1 = make_float2(acc[mt][nt][2], acc[mt][nt][3]);
        }
    }
}

// ---------------------------------------------------------------------------
// Fused RoPE + bf16 split + head-major reorder, reading fused QKV buffer.
// ---------------------------------------------------------------------------
__global__ __launch_bounds__(256) void qkv_convert()
{
    const float ASCALE = 0.08838834764831845f;
    int idx = blockIdx.x * 256 + threadIdx.x;
    int d  = idx & 63;
    int h  = (idx >> 6) & 15;
    int bs = idx >> 10;
    int b = bs >> 11, sidx = bs & (SEQ - 1);

    float invf = 1.0f / powf(10000.0f, (float)d * (1.0f / 64.0f));
    float angf = (float)g_pos[bs] * invf;
    float ss, cc;
    sincosf(angf, &ss, &cc);

    size_t src = (size_t)bs * (3 * D_MODEL) + h * HEAD_DIM;
    size_t dst = ((size_t)(b * N_HEADS + h) * SEQ + sidx) * HEAD_DIM;

    float q1 = g_qkv[src + d], q2 = g_qkv[src + d + 64];
    float rq1 = (q1 * cc - q2 * ss) * ASCALE;
    float rq2 = (q2 * cc + q1 * ss) * ASCALE;
    __nv_bfloat16 hh;
    hh = __float2bfloat16(rq1); g_qhi[dst + d] = hh;
    g_qlo[dst + d] = __float2bfloat16(rq1 - __bfloat162float(hh));
    hh = __float2bfloat16(rq2); g_qhi[dst + d + 64] = hh;
    g_qlo[dst + d + 64] = __float2bfloat16(rq2 - __bfloat162float(hh));

    float k1 = g_qkv[src + D_MODEL + d], k2 = g_qkv[src + D_MODEL + d + 64];
    float rk1 = k1 * cc - k2 * ss;
    float rk2 = k2 * cc + k1 * ss;
    hh = __float2bfloat16(rk1); g_khi[dst + d] = hh;
    g_klo[dst + d] = __float2bfloat16(rk1 - __bfloat162float(hh));
    hh = __float2bfloat16(rk2); g_khi[dst + d + 64] = hh;
    g_klo[dst + d + 64] = __float2bfloat16(rk2 - __bfloat162float(hh));

    float v1 = g_qkv[src + 2 * D_MODEL + d], v2 = g_qkv[src + 2 * D_MODEL + d + 64];
    hh = __float2bfloat16(v1); g_vhi[dst + d] = hh;
    g_vlo[dst + d] = __float2bfloat16(v1 - __bfloat162float(hh));
    hh = __float2bfloat16(v2); g_vhi[dst + d + 64] = hh;
    g_vlo[dst + d + 64] = __float2bfloat16(v2 - __bfloat162float(hh));
}

// ---------------------------------------------------------------------------
// Tensor-core flash attention, split-bf16, causal tile skipping.
// R13: software-pipelined K/V loads — V[kt] latency hides behind S+softmax,
// K[kt+1] behind softmax+PV (split cp.async commit groups).
// ---------------------------------------------------------------------------
constexpr int AT_HB  = 16384;
constexpr int AT_TEN = 32768;
constexpr int ATQ = 0;
constexpr int ATK = 2 * AT_TEN;
constexpr int ATV = 4 * AT_TEN;
constexpr int ATTN_SMEM2 = 6 * AT_TEN;   // 196608

__device__ __forceinline__ void at_load_tile(uint32_t dst,
                                             const __nv_bfloat16* __restrict__ src,
                                             int tid)
{
    const char* gb = (const char*)src;
#pragma unroll
    for (int it = 0; it < 8; it++) {
        int ci = it * 256 + tid;
        int r = ci >> 4, g = ci & 15;
        uint32_t so = dst + (g >> 3) * AT_HB + SMEM_SWIZZLE_128B(r * 128 + (g & 7) * 16);
        CP_ASYNC16(so, gb + (size_t)r * 256 + g * 16);
    }
}

__global__ __launch_bounds__(256) void attn_mma(__nv_bfloat16* __restrict__ Ahi,
                                                __nv_bfloat16* __restrict__ Alo)
{
    extern __shared__ char sm[];
    const uint32_t smb = smem_to_u32(sm);
    const int tid = threadIdx.x, wid = tid >> 5, lane = tid & 31;
    const int qt = (int)(gridDim.x - 1) - (int)blockIdx.x;   // heavy tiles first
    const int bh = blockIdx.y;
    const int b = bh >> 4, h = bh & 15;
    const size_t hb = (size_t)bh * SEQ * HEAD_DIM;
    const int* posB = g_pos + b * SEQ;
    const int q0 = qt * 128;

    // group 1: Q hi/lo
    at_load_tile(smb + ATQ, g_qhi + hb + (size_t)q0 * 128, tid);
    at_load_tile(smb + ATQ + AT_TEN, g_qlo + hb + (size_t)q0 * 128, tid);
    CP_COMMIT();
    // group 2: K[0]
    at_load_tile(smb + ATK, g_khi + hb, tid);
    at_load_tile(smb + ATK + AT_TEN, g_klo + hb, tid);
    CP_COMMIT();
    // group 3: V[0]
    at_load_tile(smb + ATV, g_vhi + hb, tid);
    at_load_tile(smb + ATV + AT_TEN, g_vlo + hb, tid);
    CP_COMMIT();

    const int pqmax = __ldg(posB + q0 + 127);
    int nkt = qt + 1;
    for (int t2 = qt + 1; t2 < (int)gridDim.x; t2++) {
        if (__ldg(posB + t2 * 128) <= pqmax) nkt++; else break;
    }

    const int r0 = wid * 16 + (lane >> 2);
    const int pq0 = __ldg(posB + q0 + r0);
    const int pq1 = __ldg(posB + q0 + r0 + 8);

    float oacc[16][4];
#pragma unroll
    for (int i = 0; i < 16; i++)
#pragma unroll
        for (int j = 0; j < 4; j++) oacc[i][j] = 0.0f;
    float mA = -INFINITY, mB = -INFINITY, lA = 0.0f, lB = 0.0f;

    const int a_r = (lane & 7) + ((lane >> 3) & 1) * 8;
    const int a_c = (lane >> 4) * 8;
    const int b_r = (lane & 7) + ((lane >> 4) & 1) * 8;
    const int b_c = ((lane >> 3) & 1) * 8;
    const int t_r = (lane & 7) + ((lane >> 3) & 1) * 8;
    const int t_c = (lane >> 4) * 8;

    for (int kt = 0; kt < nkt; kt++) {
        const bool more = (kt + 1 < nkt);

        // K[kt] resident (V[kt] may still be in flight)
        CP_WAIT1();
        __syncthreads();

        // ---- S = Q K^T (3-term split) ----
        float sS[16][4];
#pragma unroll
        for (int i = 0; i < 16; i++)
#pragma unroll
            for (int j = 0; j < 4; j++) sS[i][j] = 0.0f;

#pragma unroll
        for (int ks = 0; ks < 8; ks++) {
            const uint32_t halfoff = (ks >> 2) * AT_HB;
            const int kbh = (ks & 3) * 16;
            const uint32_t aoff = SMEM_SWIZZLE_128B((wid * 16 + a_r) * 128 + (kbh + a_c) * 2);
            uint32_t ah[4], al[4];
            ldsm_x4(ah, smb + ATQ + halfoff + aoff);
            ldsm_x4(al, smb + ATQ + AT_TEN + halfoff + aoff);
#pragma unroll
            for (int nb = 0; nb < 8; nb++) {
                const uint32_t boff = SMEM_SWIZZLE_128B((nb * 16 + b_r) * 128 + (kbh + b_c) * 2);
                uint32_t kh4[4], kl4[4];
                ldsm_x4(kh4, smb + ATK + halfoff + boff);
                ldsm_x4(kl4, smb + ATK + AT_TEN + halfoff + boff);
                mma16816(sS[nb * 2], ah, kh4);
                mma16816(sS[nb * 2], ah, kl4);
                mma16816(sS[nb * 2], al, kh4);
                mma16816(sS[nb * 2 + 1], ah, kh4 + 2);
                mma16816(sS[nb * 2 + 1], ah, kl4 + 2);
                mma16816(sS[nb * 2 + 1], al, kh4 + 2);
            }
        }

        // All warps done reading K smem -> start prefetching K[kt+1]
        __syncthreads();
        if (more) {
            const size_t kn = hb + (size_t)(kt + 1) * 128 * 128;
            at_load_tile(smb + ATK, g_khi + kn, tid);
            at_load_tile(smb + ATK + AT_TEN, g_klo + kn, tid);
            CP_COMMIT();        // pending: V[kt], K[kt+1]
        }

        // ---- mask (register work, overlaps K prefetch) ----
        if (kt >= qt) {
            const int cb = kt * 128 + (lane & 3) * 2;
#pragma unroll
            for (int nt = 0; nt < 16; nt++) {
                int c0 = cb + nt * 8;
                int pk0 = __ldg(posB + c0), pk1 = __ldg(posB + c0 + 1);
                if (pq0 < pk0) sS[nt][0] = -1e30f;
                if (pq0 < pk1) sS[nt][1] = -1e30f;
                if (pq1 < pk0) sS[nt][2] = -1e30f;
                if (pq1 < pk1) sS[nt][3] = -1e30f;
            }
        }

        // ---- online softmax ----
        float mxA = -1e30f, mxB = -1e30f;
#pragma unroll
        for (int nt = 0; nt < 16; nt++) {
            mxA = fmaxf(mxA, fmaxf(sS[nt][0], sS[nt][1]));
            mxB = fmaxf(mxB, fmaxf(sS[nt][2], sS[nt][3]));
        }
        mxA = fmaxf(mxA, __shfl_xor_sync(0xFFFFFFFFu, mxA, 1));
        mxA = fmaxf(mxA, __shfl_xor_sync(0xFFFFFFFFu, mxA, 2));
        mxB = fmaxf(mxB, __shfl_xor_sync(0xFFFFFFFFu, mxB, 1));
        mxB = fmaxf(mxB, __shfl_xor_sync(0xFFFFFFFFu, mxB, 2));
        const float mnA = fmaxf(mA, mxA), mnB = fmaxf(mB, mxB);
        const float alA = __expf(mA - mnA), alB = __expf(mB - mnB);
        mA = mnA; mB = mnB;
        float smA = 0.0f, smB = 0.0f;
#pragma unroll
        for (int nt = 0; nt < 16; nt++) {
            sS[nt][0] = __expf(sS[nt][0] - mnA);
            sS[nt][1] = __expf(sS[nt][1] - mnA);
            sS[nt][2] = __expf(sS[nt][2] - mnB);
            sS[nt][3] = __expf(sS[nt][3] - mnB);
            smA += sS[nt][0] + sS[nt][1];
            smB += sS[nt][2] + sS[nt][3];
        }
        smA += __shfl_xor_sync(0xFFFFFFFFu, smA, 1);
        smA += __shfl_xor_sync(0xFFFFFFFFu, smA, 2);
        smB += __shfl_xor_sync(0xFFFFFFFFu, smB, 1);
        smB += __shfl_xor_sync(0xFFFFFFFFu, smB, 2);
        lA = lA * alA + smA;
        lB = lB * alB + smB;
#pragma unroll
        for (int nt = 0; nt < 16; nt++) {
            oacc[nt][0] *= alA; oacc[nt][1] *= alA;
            oacc[nt][2] *= alB; oacc[nt][3] *= alB;
        }

        // V[kt] resident (K[kt+1] may still be in flight)
        if (more) CP_WAIT1(); else CP_WAIT0();
        __syncthreads();

        // ---- O += P V (3-term split) ----
#pragma unroll
        for (int kv = 0; kv < 8; kv++) {
            uint32_t phi[4], plo[4];
            split2(sS[kv * 2][0], sS[kv * 2][1], phi[0], plo[0]);
            split2(sS[kv * 2][2], sS[kv * 2][3], phi[1], plo[1]);
            split2(sS[kv * 2 + 1][0], sS[kv * 2 + 1][1], phi[2], plo[2]);
            split2(sS[kv * 2 + 1][2], sS[kv * 2 + 1][3], phi[3], plo[3]);
#pragma unroll
            for (int dt = 0; dt < 8; dt++) {
                const int colb = dt * 16 + t_c;
                const uint32_t voff = (colb >> 6) * AT_HB +
                    SMEM_SWIZZLE_128B((kv * 16 + t_r) * 128 + (colb & 63) * 2);
                uint32_t vh4[4], vl4[4];
                ldsm_x4_t(vh4, smb + ATV + voff);
                ldsm_x4_t(vl4, smb + ATV + AT_TEN + voff);
                mma16816(oacc[dt * 2], phi, vh4);
                mma16816(oacc[dt * 2], phi, vl4);
                mma16816(oacc[dt * 2], plo, vh4);
                mma16816(oacc[dt * 2 + 1], phi, vh4 + 2);
                mma16816(oacc[dt * 2 + 1], phi, vl4 + 2);
                mma16816(oacc[dt * 2 + 1], plo, vh4 + 2);
            }
        }

        // All warps done reading V smem -> start prefetching V[kt+1]
        if (more) {
            __syncthreads();
            const size_t vn = hb + (size_t)(kt + 1) * 128 * 128;
            at_load_tile(smb + ATV, g_vhi + vn, tid);
            at_load_tile(smb + ATV + AT_TEN, g_vlo + vn, tid);
            CP_COMMIT();        // pending: K[kt+1], V[kt+1]
        }
    }

    // ---- epilogue ----
    const float liA = 1.0f / lA, liB = 1.0f / lB;
    const size_t rowA = (size_t)b * SEQ + q0 + r0;
    const size_t rowB = rowA + 8;
    const int cb = h * HEAD_DIM + (lane & 3) * 2;
#pragma unroll
    for (int nt = 0; nt < 16; nt++) {
        uint32_t hi01, lo01, hi23, lo23;
        split2(oacc[nt][0] * liA, oacc[nt][1] * liA, hi01, lo01);
        split2(oacc[nt][2] * liB, oacc[nt][3] * liB, hi23, lo23);
        const size_t oA = rowA * D_MODEL + cb + nt * 8;
        const size_t oB = rowB * D_MODEL + cb + nt * 8;
        *(uint32_t*)(Ahi + oA) = hi01;
        *(uint32_t*)(Alo + oA) = lo01;
        *(uint32_t*)(Ahi + oB) = hi23;
        *(uint32_t*)(Alo + oB) = lo23;
    }
}

// ---------------------------------------------------------------------------
extern "C" void kernel_launch(void* const* d_in, const int* in_sizes, int n_in,
                              void* d_out, int out_size)
{
    int idx_x = -1, idx_pos = -1;
    for (int i = 0; i < n_in; i++) {
        if (in_sizes[i] == MROWS * D_MODEL) idx_x = i;
        if (in_sizes[i] == MROWS)           idx_pos = i;
    }

    const float* x;
    const float *wq, *wk, *wv, *wo;
    const int* posraw;

    if (idx_x == 0) {   // dict order: x, Wq, Wk, Wv, Wo, pos
        x  = (const float*)d_in[0];
        wq = (const float*)d_in[1];
        wk = (const float*)d_in[2];
        wv = (const float*)d_in[3];
        wo = (const float*)d_in[4];
        posraw = (const int*)d_in[idx_pos >= 0 ? idx_pos : 5];
    } else {            // alphabetical: Wk, Wo, Wq, Wv, pos, x
        wk = (const float*)d_in[0];
        wo = (const float*)d_in[1];
        wq = (const float*)d_in[2];
        wv = (const float*)d_in[3];
        posraw = (const int*)d_in[idx_pos >= 0 ? idx_pos : 4];
        x  = (const float*)d_in[idx_x >= 0 ? idx_x : 5];
    }

    float* out = (float*)d_out;

    float* qkv;
    cudaGetSymbolAddress((void**)&qkv, g_qkv);
    __nv_bfloat16 *xhi, *xlo, *ahi, *alo, *wThi, *wTlo;
    cudaGetSymbolAddress((void**)&xhi, g_xhi);
    cudaGetSymbolAddress((void**)&xlo, g_xlo);
    cudaGetSymbolAddress((void**)&ahi, g_ahi);
    cudaGetSymbolAddress((void**)&alo, g_alo);
    cudaGetSymbolAddress((void**)&wThi, g_wThi);
    cudaGetSymbolAddress((void**)&wTlo, g_wTlo);
    const size_t WSZ = (size_t)D_MODEL * D_MODEL;

    cudaFuncSetAttribute(gemm_mma, cudaFuncAttributeMaxDynamicSharedMemorySize, GEMM_SMEM);
    cudaFuncSetAttribute(attn_mma, cudaFuncAttributeMaxDynamicSharedMemorySize, ATTN_SMEM2);

    split_fp32<<<(MROWS * D_MODEL) / 256, 256>>>(x, xhi, xlo);
    dim3 gT4(D_MODEL / 32, D_MODEL / 32, 4);
    transpose_split4<<<gT4, 256>>>(wq, wk, wv, wo, wThi, wTlo);

    // Fused Q/K/V projection: N = 3*D_MODEL (weights contiguous)
    dim3 gQKV(3 * D_MODEL / 128, MROWS / 128);
    gemm_mma<<<gQKV, 256, GEMM_SMEM>>>(xhi, xlo, wThi, wTlo, qkv,
                                       MROWS, 3 * D_MODEL, D_MODEL);

    pos_norm_kernel<<<1, 1024>>>(posraw);

    // RoPE + split + head-major reorder (fused)
    qkv_convert<<<(MROWS * N_HEADS * 64) / 256, 256>>>();

    // Tensor-core flash attention -> ahi/alo (bf16 split, [bs][D] layout)
    attn_mma<<<dim3(SEQ / 128, BATCH * N_HEADS), 256, ATTN_SMEM2>>>(ahi, alo);

    // Output projection
    dim3 gG(D_MODEL / 128, MROWS / 128);
    gemm_mma<<<gG, 256, GEMM_SMEM>>>(ahi, alo, wThi + 3 * WSZ, wTlo + 3 * WSZ, out,
                                     MROWS, D_MODEL, D_MODEL);
}

// round 17
// speedup vs baseline: 5.0127x; 1.0580x over previous
#include <cuda_runtime.h>
#include <cuda_bf16.h>
#include <math.h>
#include <stdint.h>

#define D_MODEL 2048
#define N_HEADS 16
#define HEAD_DIM 128
#define BATCH 2
#define SEQ 2048
#define MROWS (BATCH*SEQ)   /* 4096 */

// ---------------------------------------------------------------------------
// Scratch (static device globals)
// ---------------------------------------------------------------------------
__device__ float g_qkv[(size_t)MROWS * 3 * D_MODEL];   // QKV out; later reused as attn fp32 out
__device__ int   g_pos[MROWS];
__device__ float g_woT[(size_t)D_MODEL * D_MODEL];     // Wo^T, tf32-rounded fp32

__device__ __nv_bfloat16 g_xhi[(size_t)MROWS * D_MODEL];
__device__ __nv_bfloat16 g_xlo[(size_t)MROWS * D_MODEL];
__device__ __nv_bfloat16 g_wThi[3][(size_t)D_MODEL * D_MODEL];
__device__ __nv_bfloat16 g_wTlo[3][(size_t)D_MODEL * D_MODEL];
// head-major [(b*16+h)][s][d] bf16 hi/lo operands for attention
__device__ __nv_bfloat16 g_qhi[(size_t)MROWS * D_MODEL];
__device__ __nv_bfloat16 g_qlo[(size_t)MROWS * D_MODEL];
__device__ __nv_bfloat16 g_khi[(size_t)MROWS * D_MODEL];
__device__ __nv_bfloat16 g_klo[(size_t)MROWS * D_MODEL];
__device__ __nv_bfloat16 g_vhi[(size_t)MROWS * D_MODEL];
__device__ __nv_bfloat16 g_vlo[(size_t)MROWS * D_MODEL];

// ---------------------------------------------------------------------------
// Helpers (baseline PTX only)
// ---------------------------------------------------------------------------
__device__ __forceinline__ uint32_t smem_to_u32(const void* p) {
    uint32_t a;
    asm("{ .reg .u64 t; cvta.to.shared.u64 t, %1; cvt.u32.u64 %0, t; }"
        : "=r"(a) : "l"(p));
    return a;
}
#define SMEM_SWIZZLE_128B(off) ((off) ^ (((off) >> 3) & 0x70))

__device__ __forceinline__ void ldsm_x4(uint32_t* r, uint32_t addr) {
    asm volatile("ldmatrix.sync.aligned.m8n8.x4.shared.b16 {%0,%1,%2,%3}, [%4];"
        : "=r"(r[0]), "=r"(r[1]), "=r"(r[2]), "=r"(r[3]) : "r"(addr));
}
__device__ __forceinline__ void ldsm_x4_t(uint32_t* r, uint32_t addr) {
    asm volatile("ldmatrix.sync.aligned.m8n8.x4.trans.shared.b16 {%0,%1,%2,%3}, [%4];"
        : "=r"(r[0]), "=r"(r[1]), "=r"(r[2]), "=r"(r[3]) : "r"(addr));
}
__device__ __forceinline__ void mma16816(float* c, const uint32_t* a, const uint32_t* b) {
    asm volatile("mma.sync.aligned.m16n8k16.row.col.f32.bf16.bf16.f32 "
        "{%0,%1,%2,%3}, {%4,%5,%6,%7}, {%8,%9}, {%0,%1,%2,%3};"
        : "+f"(c[0]), "+f"(c[1]), "+f"(c[2]), "+f"(c[3])
        : "r"(a[0]), "r"(a[1]), "r"(a[2]), "r"(a[3]), "r"(b[0]), "r"(b[1]));
}
__device__ __forceinline__ void mma_tf32(float* c, const uint32_t* a, const uint32_t* b) {
    asm volatile("mma.sync.aligned.m16n8k8.row.col.f32.tf32.tf32.f32 "
        "{%0,%1,%2,%3}, {%4,%5,%6,%7}, {%8,%9}, {%0,%1,%2,%3};"
        : "+f"(c[0]), "+f"(c[1]), "+f"(c[2]), "+f"(c[3])
        : "r"(a[0]), "r"(a[1]), "r"(a[2]), "r"(a[3]), "r"(b[0]), "r"(b[1]));
}
__device__ __forceinline__ uint32_t f2tf32(float x) {
    uint32_t u;
    asm("cvt.rna.tf32.f32 %0, %1;" : "=r"(u) : "f"(x));
    return u;
}
#define CP_ASYNC16(sm, gp) \
    asm volatile("cp.async.cg.shared.global [%0], [%1], 16;" :: "r"(sm), "l"(gp))
#define CP_COMMIT() asm volatile("cp.async.commit_group;" ::: "memory")
#define CP_WAIT1()  asm volatile("cp.async.wait_group 1;" ::: "memory")
#define CP_WAIT0()  asm volatile("cp.async.wait_group 0;" ::: "memory")

// split two floats into packed bf16x2 hi and lo
__device__ __forceinline__ void split2(float x, float y, uint32_t& hi, uint32_t& lo) {
    __nv_bfloat162 h = __floats2bfloat162_rn(x, y);
    float hx = __bfloat162float(h.x);
    float hy = __bfloat162float(h.y);
    __nv_bfloat162 l = __floats2bfloat162_rn(x - hx, y - hy);
    hi = *(uint32_t*)&h;
    lo = *(uint32_t*)&l;
}

// ---------------------------------------------------------------------------
// fp32 -> (hi, lo) bf16 split; last block instead does position normalization
// ---------------------------------------------------------------------------
__global__ __launch_bounds__(256) void split_fp32_pos(const float* __restrict__ in,
                                                      __nv_bfloat16* __restrict__ hi,
                                                      __nv_bfloat16* __restrict__ lo,
                                                      const int* __restrict__ raw)
{
    if (blockIdx.x == gridDim.x - 1) {
        // position normalization: int64-vs-int32 dtype detection
        __shared__ int s_or[8];
        const int tid = threadIdx.x;
        int any = 0;
        for (int i = tid; i < 2048; i += 256) any |= raw[2 * i + 1];
#pragma unroll
        for (int o = 16; o; o >>= 1) any |= __shfl_down_sync(0xFFFFFFFFu, any, o);
        if ((tid & 31) == 0) s_or[tid >> 5] = any;
        __syncthreads();
        if (tid == 0) {
            int v = 0;
#pragma unroll
            for (int w = 0; w < 8; w++) v |= s_or[w];
            s_or[0] = v;
        }
        __syncthreads();
        const bool is64 = (s_or[0] == 0);
        for (int i = tid; i < MROWS; i += 256)
            g_pos[i] = is64 ? raw[2 * i] : raw[i];
        return;
    }
    int i = blockIdx.x * 256 + threadIdx.x;
    float v = in[i];
    __nv_bfloat16 h = __float2bfloat16(v);
    hi[i] = h;
    lo[i] = __float2bfloat16(v - __bfloat162float(h));
}

// ---------------------------------------------------------------------------
// Three W[K][N] fp32 -> W^T[N][K] (hi, lo) bf16 splits (Wq, Wk, Wv)
// ---------------------------------------------------------------------------
__global__ __launch_bounds__(256) void transpose_split3(const float* __restrict__ w0,
                                                        const float* __restrict__ w1,
                                                        const float* __restrict__ w2,
                                                        __nv_bfloat16* __restrict__ hiT,
                                                        __nv_bfloat16* __restrict__ loT)
{
    __shared__ float t[32][33];
    const int z = blockIdx.z;
    const float* W = (z == 0) ? w0 : (z == 1) ? w1 : w2;
    const size_t WSZ = (size_t)D_MODEL * D_MODEL;
    __nv_bfloat16* hi = hiT + z * WSZ;
    __nv_bfloat16* lo = loT + z * WSZ;

    const int n0 = blockIdx.x * 32, k0 = blockIdx.y * 32;
    const int tx = threadIdx.x & 31, ty = threadIdx.x >> 5;
#pragma unroll
    for (int r = ty; r < 32; r += 8)
        t[r][tx] = W[(size_t)(k0 + r) * D_MODEL + n0 + tx];
    __syncthreads();
#pragma unroll
    for (int r = ty; r < 32; r += 8) {
        float v = t[tx][r];
        __nv_bfloat16 h = __float2bfloat16(v);
        size_t o = (size_t)(n0 + r) * D_MODEL + k0 + tx;
        hi[o] = h;
        lo[o] = __float2bfloat16(v - __bfloat162float(h));
    }
}

// ---------------------------------------------------------------------------
// Wo[K][N] fp32 -> Wo^T[N][K] fp32 (tf32-rounded)
// ---------------------------------------------------------------------------
__global__ __launch_bounds__(256) void transpose_tf32(const float* __restrict__ W,
                                                      float* __restrict__ outT)
{
    __shared__ float t[32][33];
    const int n0 = blockIdx.x * 32, k0 = blockIdx.y * 32;
    const int tx = threadIdx.x & 31, ty = threadIdx.x >> 5;
#pragma unroll
    for (int r = ty; r < 32; r += 8)
        t[r][tx] = W[(size_t)(k0 + r) * D_MODEL + n0 + tx];
    __syncthreads();
#pragma unroll
    for (int r = ty; r < 32; r += 8) {
        uint32_t u = f2tf32(t[tx][r]);
        *(uint32_t*)&outT[(size_t)(n0 + r) * D_MODEL + k0 + tx] = u;
    }
}

// ---------------------------------------------------------------------------
// mma.sync bf16 split GEMM (proven R9 structure) — used for fused QKV proj
// ---------------------------------------------------------------------------
constexpr int GSTAGES = 3;
constexpr int GT_BYTES = 128 * 64 * 2;
constexpr int GSTAGE_BYTES = 4 * GT_BYTES;
constexpr int GEMM_SMEM = GSTAGES * GSTAGE_BYTES;

__device__ __forceinline__ void g_load_stage(uint32_t smst,
                                             const __nv_bfloat16* __restrict__ Ahi,
                                             const __nv_bfloat16* __restrict__ Alo,
                                             const __nv_bfloat16* __restrict__ Bhi,
                                             const __nv_bfloat16* __restrict__ Blo,
                                             int tileM, int tileN, int K, int kc, int tid)
{
    const __nv_bfloat16* gsrc[4];
    gsrc[0] = Ahi + (size_t)tileM * K + kc * 64;
    gsrc[1] = Alo + (size_t)tileM * K + kc * 64;
    gsrc[2] = Bhi + (size_t)tileN * K + kc * 64;
    gsrc[3] = Blo + (size_t)tileN * K + kc * 64;
    const size_t rs = (size_t)K * 2;
#pragma unroll
    for (int tsr = 0; tsr < 4; tsr++) {
        const char* gb = (const char*)gsrc[tsr];
        uint32_t sbase = smst + tsr * GT_BYTES;
#pragma unroll
        for (int it = 0; it < 4; it++) {
            int idx = it * 256 + tid;
            int r = idx >> 3, g = idx & 7;
            uint32_t so = sbase + SMEM_SWIZZLE_128B(r * 128 + g * 16);
            const char* gp = gb + (size_t)r * rs + g * 16;
            CP_ASYNC16(so, gp);
        }
    }
}

__global__ __launch_bounds__(256) void gemm_mma(const __nv_bfloat16* __restrict__ Ahi,
                                                const __nv_bfloat16* __restrict__ Alo,
                                                const __nv_bfloat16* __restrict__ Bhi,
                                                const __nv_bfloat16* __restrict__ Blo,
                                                float* __restrict__ C,
                                                int M, int N, int K)
{
    extern __shared__ char sm[];
    const uint32_t smb = smem_to_u32(sm);
    const int tid = threadIdx.x;
    const int wid = tid >> 5, lane = tid & 31;
    const int warp_m = wid & 1;
    const int warp_n = wid >> 1;
    const int tileN = blockIdx.x * 128, tileM = blockIdx.y * 128;

    float acc[4][4][4];
#pragma unroll
    for (int a = 0; a < 4; a++)
#pragma unroll
        for (int b = 0; b < 4; b++)
#pragma unroll
            for (int c = 0; c < 4; c++) acc[a][b][c] = 0.0f;

    const int niter = K / 64;

    g_load_stage(smb + 0 * GSTAGE_BYTES, Ahi, Alo, Bhi, Blo, tileM, tileN, K, 0, tid);
    CP_COMMIT();
    g_load_stage(smb + 1 * GSTAGE_BYTES, Ahi, Alo, Bhi, Blo, tileM, tileN, K, 1, tid);
    CP_COMMIT();

    const int a_r = (lane & 7) + ((lane >> 3) & 1) * 8;
    const int a_c = (lane >> 4) * 8;
    const int b_r = (lane & 7) + ((lane >> 4) & 1) * 8;
    const int b_c = ((lane >> 3) & 1) * 8;

    for (int i = 0; i < niter; i++) {
        CP_WAIT1();
        __syncthreads();

        if (i + 2 < niter)
            g_load_stage(smb + ((i + 2) % GSTAGES) * GSTAGE_BYTES,
                         Ahi, Alo, Bhi, Blo, tileM, tileN, K, i + 2, tid);
        CP_COMMIT();

        const uint32_t st = smb + (i % GSTAGES) * GSTAGE_BYTES;
        const uint32_t aHiB = st, aLoB = st + GT_BYTES;
        const uint32_t bHiB = st + 2 * GT_BYTES, bLoB = st + 3 * GT_BYTES;

#pragma unroll
        for (int ks = 0; ks < 4; ks++) {
            const int kb = ks * 16;
            uint32_t bh[4][2], bl[4][2];
#pragma unroll
            for (int np = 0; np < 2; np++) {
                const int n_base = warp_n * 32 + np * 16;
                uint32_t off = SMEM_SWIZZLE_128B((n_base + b_r) * 128 + (kb + b_c) * 2);
                uint32_t r4[4];
                ldsm_x4(r4, bHiB + off);
                bh[np * 2][0] = r4[0]; bh[np * 2][1] = r4[1];
                bh[np * 2 + 1][0] = r4[2]; bh[np * 2 + 1][1] = r4[3];
                ldsm_x4(r4, bLoB + off);
                bl[np * 2][0] = r4[0]; bl[np * 2][1] = r4[1];
                bl[np * 2 + 1][0] = r4[2]; bl[np * 2 + 1][1] = r4[3];
            }
#pragma unroll
            for (int mt = 0; mt < 4; mt++) {
                const int m_base = warp_m * 64 + mt * 16;
                uint32_t off = SMEM_SWIZZLE_128B((m_base + a_r) * 128 + (kb + a_c) * 2);
                uint32_t ah[4], al[4];
                ldsm_x4(ah, aHiB + off);
                ldsm_x4(al, aLoB + off);
#pragma unroll
                for (int nt = 0; nt < 4; nt++) {
                    mma16816(acc[mt][nt], ah, bh[nt]);
                    mma16816(acc[mt][nt], ah, bl[nt]);
                    mma16816(acc[mt][nt], al, bh[nt]);
                }
            }
        }
    }

    const int er = lane >> 2;
    const int ec = (lane & 3) * 2;
#pragma unroll
    for (int mt = 0; mt < 4; mt++) {
        const int row0 = tileM + warp_m * 64 + mt * 16 + er;
#pragma unroll
        for (int nt = 0; nt < 4; nt++) {
            const int col = tileN + warp_n * 32 + nt * 8 + ec;
            float* p0 = C + (size_t)row0 * N + col;
            float* p1 = C + (size_t)(row0 + 8) * N + col;
            *(float2*)p0 = make_float2(acc[mt][nt][0], acc[mt][nt][1]);
            *(float2*)p1 = make_float2(acc[mt][nt][2], acc[mt][nt][3]);
        }
    }
}

// ---------------------------------------------------------------------------
// tf32 single-pass GEMM (out projection): C[M,N] = A[M,K]f32 @ B[N,K]f32^T
// Operands pre-rounded to tf32 (rna) by producers. 128x128 CTA, BK=32,
// 3-stage cp.async, ldmatrix-based tf32 fragments on SW128 layout.
// ---------------------------------------------------------------------------
constexpr int TSTAGES = 3;
constexpr int TT_BYTES = 128 * 128;             // 16KB (128 rows x 32 floats)
constexpr int TSTAGE_BYTES = 2 * TT_BYTES;      // 32KB
constexpr int TF32_SMEM = TSTAGES * TSTAGE_BYTES;  // 96KB

__device__ __forceinline__ void t_load_stage(uint32_t smst,
                                             const float* __restrict__ A,
                                             const float* __restrict__ B,
                                             int tileM, int tileN, int K, int kc, int tid)
{
    const char* gsrc[2];
    gsrc[0] = (const char*)(A + (size_t)tileM * K + kc * 32);
    gsrc[1] = (const char*)(B + (size_t)tileN * K + kc * 32);
    const size_t rs = (size_t)K * 4;
#pragma unroll
    for (int tsr = 0; tsr < 2; tsr++) {
        const char* gb = gsrc[tsr];
        uint32_t sbase = smst + tsr * TT_BYTES;
#pragma unroll
        for (int it = 0; it < 4; it++) {
            int idx = it * 256 + tid;
            int r = idx >> 3, g = idx & 7;
            uint32_t so = sbase + SMEM_SWIZZLE_128B(r * 128 + g * 16);
            CP_ASYNC16(so, gb + (size_t)r * rs + g * 16);
        }
    }
}

__global__ __launch_bounds__(256) void gemm_tf32(const float* __restrict__ A,
                                                 const float* __restrict__ B,
                                                 float* __restrict__ C,
                                                 int M, int N, int K)
{
    extern __shared__ char sm[];
    const uint32_t smb = smem_to_u32(sm);
    const int tid = threadIdx.x;
    const int wid = tid >> 5, lane = tid & 31;
    const int warp_m = wid & 1;          // 64-row slab
    const int warp_n = wid >> 1;         // 32-col slab
    const int tileN = blockIdx.x * 128, tileM = blockIdx.y * 128;

    float acc[4][4][4];
#pragma unroll
    for (int a = 0; a < 4; a++)
#pragma unroll
        for (int b = 0; b < 4; b++)
#pragma unroll
            for (int c = 0; c < 4; c++) acc[a][b][c] = 0.0f;

    const int niter = K / 32;            // 64

    t_load_stage(smb + 0 * TSTAGE_BYTES, A, B, tileM, tileN, K, 0, tid);
    CP_COMMIT();
    t_load_stage(smb + 1 * TSTAGE_BYTES, A, B, tileM, tileN, K, 1, tid);
    CP_COMMIT();

    // A x4: lanes 0-7 rows m+0..7 half0; 8-15 rows m+8..15 half0;
    //       16-23 rows m+0..7 half1; 24-31 rows m+8..15 half1
    const int ta_r = (lane & 7) + ((lane >> 3) & 1) * 8;
    const int ta_h = (lane >> 4);                      // 16B half within k8 slice
    // B x4 (covers an nt-pair): lanes 0-7 rows n+0..7 half0; 8-15 rows n+0..7 half1;
    //       16-23 rows n+8..15 half0; 24-31 rows n+8..15 half1
    const int tb_r = (lane & 7) + ((lane >> 4) & 1) * 8;
    const int tb_h = (lane >> 3) & 1;

    for (int i = 0; i < niter; i++) {
        CP_WAIT1();
        __syncthreads();

        if (i + 2 < niter)
            t_load_stage(smb + ((i + 2) % TSTAGES) * TSTAGE_BYTES,
                         A, B, tileM, tileN, K, i + 2, tid);
        CP_COMMIT();

        const uint32_t st = smb + (i % TSTAGES) * TSTAGE_BYTES;
        const uint32_t aB = st, bB = st + TT_BYTES;

#pragma unroll
        for (int ks = 0; ks < 4; ks++) {          // 4 k8 steps per BK=32
            const int kb = ks * 32;               // byte offset within 128B row
            uint32_t bf[4][2];
#pragma unroll
            for (int p = 0; p < 2; p++) {
                const int n_base = warp_n * 32 + p * 16;
                uint32_t off = SMEM_SWIZZLE_128B((n_base + tb_r) * 128 + kb + tb_h * 16);
                uint32_t r4[4];
                ldsm_x4(r4, bB + off);
                bf[p * 2][0] = r4[0]; bf[p * 2][1] = r4[1];
                bf[p * 2 + 1][0] = r4[2]; bf[p * 2 + 1][1] = r4[3];
            }
#pragma unroll
            for (int mt = 0; mt < 4; mt++) {
                const int m_base = warp_m * 64 + mt * 16;
                uint32_t off = SMEM_SWIZZLE_128B((m_base + ta_r) * 128 + kb + ta_h * 16);
                uint32_t af[4];
                ldsm_x4(af, aB + off);
#pragma unroll
                for (int nt = 0; nt < 4; nt++)
                    mma_tf32(acc[mt][nt], af, bf[nt]);
            }
        }
    }

    const int er = lane >> 2;
    const int ec = (lane & 3) * 2;
#pragma unroll
    for (int mt = 0; mt < 4; mt++) {
        const int row0 = tileM + warp_m * 64 + mt * 16 + er;
#pragma unroll
        for (int nt = 0; nt < 4; nt++) {
            const int col = tileN + warp_n * 32 + nt * 8 + ec;
            float* p0 = C + (size_t)row0 * N + col;
            float* p1 = C + (size_t)(row0 + 8) * N + col;
            *(float2*)p0 = make_float2(acc[mt][nt][0], acc[mt][nt][1]);
            *(float2*)p1 = make_float2(acc[mt][nt][2], acc[mt][nt][3]);
        }
    }
}

// ---------------------------------------------------------------------------
// Fused RoPE + bf16 split + head-major reorder, reading fused QKV buffer.
// ---------------------------------------------------------------------------
__global__ __launch_bounds__(256) void qkv_convert()
{
    const float ASCALE = 0.08838834764831845f;
    int idx = blockIdx.x * 256 + threadIdx.x;
    int d  = idx & 63;
    int h  = (idx >> 6) & 15;
    int bs = idx >> 10;
    int b = bs >> 11, sidx = bs & (SEQ - 1);

    float invf = 1.0f / powf(10000.0f, (float)d * (1.0f / 64.0f));
    float angf = (float)g_pos[bs] * invf;
    float ss, cc;
    sincosf(angf, &ss, &cc);

    size_t src = (size_t)bs * (3 * D_MODEL) + h * HEAD_DIM;
    size_t dst = ((size_t)(b * N_HEADS + h) * SEQ + sidx) * HEAD_DIM;

    float q1 = g_qkv[src + d], q2 = g_qkv[src + d + 64];
    float rq1 = (q1 * cc - q2 * ss) * ASCALE;
    float rq2 = (q2 * cc + q1 * ss) * ASCALE;
    __nv_bfloat16 hh;
    hh = __float2bfloat16(rq1); g_qhi[dst + d] = hh;
    g_qlo[dst + d] = __float2bfloat16(rq1 - __bfloat162float(hh));
    hh = __float2bfloat16(rq2); g_qhi[dst + d + 64] = hh;
    g_qlo[dst + d + 64] = __float2bfloat16(rq2 - __bfloat162float(hh));

    float k1 = g_qkv[src + D_MODEL + d], k2 = g_qkv[src + D_MODEL + d + 64];
    float rk1 = k1 * cc - k2 * ss;
    float rk2 = k2 * cc + k1 * ss;
    hh = __float2bfloat16(rk1); g_khi[dst + d] = hh;
    g_klo[dst + d] = __float2bfloat16(rk1 - __bfloat162float(hh));
    hh = __float2bfloat16(rk2); g_khi[dst + d + 64] = hh;
    g_klo[dst + d + 64] = __float2bfloat16(rk2 - __bfloat162float(hh));

    float v1 = g_qkv[src + 2 * D_MODEL + d], v2 = g_qkv[src + 2 * D_MODEL + d + 64];
    hh = __float2bfloat16(v1); g_vhi[dst + d] = hh;
    g_vlo[dst + d] = __float2bfloat16(v1 - __bfloat162float(hh));
    hh = __float2bfloat16(v2); g_vhi[dst + d + 64] = hh;
    g_vlo[dst + d + 64] = __float2bfloat16(v2 - __bfloat162float(hh));
}

// ---------------------------------------------------------------------------
// Tensor-core flash attention, split-bf16, causal tile skipping, pipelined
// K/V loads (R13). Epilogue writes fp32 (tf32-rounded) into O.
// ---------------------------------------------------------------------------
constexpr int AT_HB  = 16384;
constexpr int AT_TEN = 32768;
constexpr int ATQ = 0;
constexpr int ATK = 2 * AT_TEN;
constexpr int ATV = 4 * AT_TEN;
constexpr int ATTN_SMEM2 = 6 * AT_TEN;   // 196608

__device__ __forceinline__ void at_load_tile(uint32_t dst,
                                             const __nv_bfloat16* __restrict__ src,
                                             int tid)
{
    const char* gb = (const char*)src;
#pragma unroll
    for (int it = 0; it < 8; it++) {
        int ci = it * 256 + tid;
        int r = ci >> 4, g = ci & 15;
        uint32_t so = dst + (g >> 3) * AT_HB + SMEM_SWIZZLE_128B(r * 128 + (g & 7) * 16);
        CP_ASYNC16(so, gb + (size_t)r * 256 + g * 16);
    }
}

__global__ __launch_bounds__(256) void attn_mma(float* __restrict__ O)
{
    extern __shared__ char sm[];
    const uint32_t smb = smem_to_u32(sm);
    const int tid = threadIdx.x, wid = tid >> 5, lane = tid & 31;
    const int qt = (int)(gridDim.x - 1) - (int)blockIdx.x;   // heavy tiles first
    const int bh = blockIdx.y;
    const int b = bh >> 4, h = bh & 15;
    const size_t hb = (size_t)bh * SEQ * HEAD_DIM;
    const int* posB = g_pos + b * SEQ;
    const int q0 = qt * 128;

    at_load_tile(smb + ATQ, g_qhi + hb + (size_t)q0 * 128, tid);
    at_load_tile(smb + ATQ + AT_TEN, g_qlo + hb + (size_t)q0 * 128, tid);
    CP_COMMIT();
    at_load_tile(smb + ATK, g_khi + hb, tid);
    at_load_tile(smb + ATK + AT_TEN, g_klo + hb, tid);
    CP_COMMIT();
    at_load_tile(smb + ATV, g_vhi + hb, tid);
    at_load_tile(smb + ATV + AT_TEN, g_vlo + hb, tid);
    CP_COMMIT();

    const int pqmax = __ldg(posB + q0 + 127);
    int nkt = qt + 1;
    for (int t2 = qt + 1; t2 < (int)gridDim.x; t2++) {
        if (__ldg(posB + t2 * 128) <= pqmax) nkt++; else break;
    }

    const int r0 = wid * 16 + (lane >> 2);
    const int pq0 = __ldg(posB + q0 + r0);
    const int pq1 = __ldg(posB + q0 + r0 + 8);

    float oacc[16][4];
#pragma unroll
    for (int i = 0; i < 16; i++)
#pragma unroll
        for (int j = 0; j < 4; j++) oacc[i][j] = 0.0f;
    float mA = -INFINITY, mB = -INFINITY, lA = 0.0f, lB = 0.0f;

    const int a_r = (lane & 7) + ((lane >> 3) & 1) * 8;
    const int a_c = (lane >> 4) * 8;
    const int b_r = (lane & 7) + ((lane >> 4) & 1) * 8;
    const int b_c = ((lane >> 3) & 1) * 8;
    const int t_r = (lane & 7) + ((lane >> 3) & 1) * 8;
    const int t_c = (lane >> 4) * 8;

    for (int kt = 0; kt < nkt; kt++) {
        const bool more = (kt + 1 < nkt);

        CP_WAIT1();
        __syncthreads();

        // ---- S = Q K^T (3-term split) ----
        float sS[16][4];
#pragma unroll
        for (int i = 0; i < 16; i++)
#pragma unroll
            for (int j = 0; j < 4; j++) sS[i][j] = 0.0f;

#pragma unroll
        for (int ks = 0; ks < 8; ks++) {
            const uint32_t halfoff = (ks >> 2) * AT_HB;
            const int kbh = (ks & 3) * 16;
            const uint32_t aoff = SMEM_SWIZZLE_128B((wid * 16 + a_r) * 128 + (kbh + a_c) * 2);
            uint32_t ah[4], al[4];
            ldsm_x4(ah, smb + ATQ + halfoff + aoff);
            ldsm_x4(al, smb + ATQ + AT_TEN + halfoff + aoff);
#pragma unroll
            for (int nb = 0; nb < 8; nb++) {
                const uint32_t boff = SMEM_SWIZZLE_128B((nb * 16 + b_r) * 128 + (kbh + b_c) * 2);
                uint32_t kh4[4], kl4[4];
                ldsm_x4(kh4, smb + ATK + halfoff + boff);
                ldsm_x4(kl4, smb + ATK + AT_TEN + halfoff + boff);
                mma16816(sS[nb * 2], ah, kh4);
                mma16816(sS[nb * 2], ah, kl4);
                mma16816(sS[nb * 2], al, kh4);
                mma16816(sS[nb * 2 + 1], ah, kh4 + 2);
                mma16816(sS[nb * 2 + 1], ah, kl4 + 2);
                mma16816(sS[nb * 2 + 1], al, kh4 + 2);
            }
        }

        __syncthreads();
        if (more) {
            const size_t kn = hb + (size_t)(kt + 1) * 128 * 128;
            at_load_tile(smb + ATK, g_khi + kn, tid);
            at_load_tile(smb + ATK + AT_TEN, g_klo + kn, tid);
            CP_COMMIT();
        }

        // ---- mask ----
        if (kt >= qt) {
            const int cb2 = kt * 128 + (lane & 3) * 2;
#pragma unroll
            for (int nt = 0; nt < 16; nt++) {
                int c0 = cb2 + nt * 8;
                int pk0 = __ldg(posB + c0), pk1 = __ldg(posB + c0 + 1);
                if (pq0 < pk0) sS[nt][0] = -1e30f;
                if (pq0 < pk1) sS[nt][1] = -1e30f;
                if (pq1 < pk0) sS[nt][2] = -1e30f;
                if (pq1 < pk1) sS[nt][3] = -1e30f;
            }
        }

        // ---- online softmax ----
        float mxA = -1e30f, mxB = -1e30f;
#pragma unroll
        for (int nt = 0; nt < 16; nt++) {
            mxA = fmaxf(mxA, fmaxf(sS[nt][0], sS[nt][1]));
            mxB = fmaxf(mxB, fmaxf(sS[nt][2], sS[nt][3]));
        }
        mxA = fmaxf(mxA, __shfl_xor_sync(0xFFFFFFFFu, mxA, 1));
        mxA = fmaxf(mxA, __shfl_xor_sync(0xFFFFFFFFu, mxA, 2));
        mxB = fmaxf(mxB, __shfl_xor_sync(0xFFFFFFFFu, mxB, 1));
        mxB = fmaxf(mxB, __shfl_xor_sync(0xFFFFFFFFu, mxB, 2));
        const float mnA = fmaxf(mA, mxA), mnB = fmaxf(mB, mxB);
        const float alA = __expf(mA - mnA), alB = __expf(mB - mnB);
        mA = mnA; mB = mnB;
        float smA = 0.0f, smB = 0.0f;
#pragma unroll
        for (int nt = 0; nt < 16; nt++) {
            sS[nt][0] = __expf(sS[nt][0] - mnA);
            sS[nt][1] = __expf(sS[nt][1] - mnA);
            sS[nt][2] = __expf(sS[nt][2] - mnB);
            sS[nt][3] = __expf(sS[nt][3] - mnB);
            smA += sS[nt][0] + sS[nt][1];
            smB += sS[nt][2] + sS[nt][3];
        }
        smA += __shfl_xor_sync(0xFFFFFFFFu, smA, 1);
        smA += __shfl_xor_sync(0xFFFFFFFFu, smA, 2);
        smB += __shfl_xor_sync(0xFFFFFFFFu, smB, 1);
        smB += __shfl_xor_sync(0xFFFFFFFFu, smB, 2);
        lA = lA * alA + smA;
        lB = lB * alB + smB;
#pragma unroll
        for (int nt = 0; nt < 16; nt++) {
            oacc[nt][0] *= alA; oacc[nt][1] *= alA;
            oacc[nt][2] *= alB; oacc[nt][3] *= alB;
        }

        if (more) CP_WAIT1(); else CP_WAIT0();
        __syncthreads();

        // ---- O += P V (3-term split) ----
#pragma unroll
        for (int kv = 0; kv < 8; kv++) {
            uint32_t phi[4], plo[4];
            split2(sS[kv * 2][0], sS[kv * 2][1], phi[0], plo[0]);
            split2(sS[kv * 2][2], sS[kv * 2][3], phi[1], plo[1]);
            split2(sS[kv * 2 + 1][0], sS[kv * 2 + 1][1], phi[2], plo[2]);
            split2(sS[kv * 2 + 1][2], sS[kv * 2 + 1][3], phi[3], plo[3]);
#pragma unroll
            for (int dt = 0; dt < 8; dt++) {
                const int colb = dt * 16 + t_c;
                const uint32_t voff = (colb >> 6) * AT_HB +
                    SMEM_SWIZZLE_128B((kv * 16 + t_r) * 128 + (colb & 63) * 2);
                uint32_t vh4[4], vl4[4];
                ldsm_x4_t(vh4, smb + ATV + voff);
                ldsm_x4_t(vl4, smb + ATV + AT_TEN + voff);
                mma16816(oacc[dt * 2], phi, vh4);
                mma16816(oacc[dt * 2], phi, vl4);
                mma16816(oacc[dt * 2], plo, vh4);
                mma16816(oacc[dt * 2 + 1], phi, vh4 + 2);
                mma16816(oacc[dt * 2 + 1], phi, vl4 + 2);
                mma16816(oacc[dt * 2 + 1], plo, vh4 + 2);
            }
        }

        if (more) {
            __syncthreads();
            const size_t vn = hb + (size_t)(kt + 1) * 128 * 128;
            at_load_tile(smb + ATV, g_vhi + vn, tid);
            at_load_tile(smb + ATV + AT_TEN, g_vlo + vn, tid);
            CP_COMMIT();
        }
    }

    // ---- epilogue: normalize, tf32-round, store fp32 [bs][D] ----
    const float liA = 1.0f / lA, liB = 1.0f / lB;
    const size_t rowA = (size_t)b * SEQ + q0 + r0;
    const size_t rowB = rowA + 8;
    const int cb = h * HEAD_DIM + (lane & 3) * 2;
#pragma unroll
    for (int nt = 0; nt < 16; nt++) {
        uint2 uA, uB;
        uA.x = f2tf32(oacc[nt][0] * liA);
        uA.y = f2tf32(oacc[nt][1] * liA);
        uB.x = f2tf32(oacc[nt][2] * liB);
        uB.y = f2tf32(oacc[nt][3] * liB);
        *(uint2*)(O + rowA * D_MODEL + cb + nt * 8) = uA;
        *(uint2*)(O + rowB * D_MODEL + cb + nt * 8) = uB;
    }
}

// ---------------------------------------------------------------------------
extern "C" void kernel_launch(void* const* d_in, const int* in_sizes, int n_in,
                              void* d_out, int out_size)
{
    int idx_x = -1, idx_pos = -1;
    for (int i = 0; i < n_in; i++) {
        if (in_sizes[i] == MROWS * D_MODEL) idx_x = i;
        if (in_sizes[i] == MROWS)           idx_pos = i;
    }

    const float* x;
    const float *wq, *wk, *wv, *wo;
    const int* posraw;

    if (idx_x == 0) {   // dict order: x, Wq, Wk, Wv, Wo, pos
        x  = (const float*)d_in[0];
        wq = (const float*)d_in[1];
        wk = (const float*)d_in[2];
        wv = (const float*)d_in[3];
        wo = (const float*)d_in[4];
        posraw = (const int*)d_in[idx_pos >= 0 ? idx_pos : 5];
    } else {            // alphabetical: Wk, Wo, Wq, Wv, pos, x
        wk = (const float*)d_in[0];
        wo = (const float*)d_in[1];
        wq = (const float*)d_in[2];
        wv = (const float*)d_in[3];
        posraw = (const int*)d_in[idx_pos >= 0 ? idx_pos : 4];
        x  = (const float*)d_in[idx_x >= 0 ? idx_x : 5];
    }

    float* out = (float*)d_out;

    float *qkv, *woT;
    cudaGetSymbolAddress((void**)&qkv, g_qkv);
    cudaGetSymbolAddress((void**)&woT, g_woT);
    __nv_bfloat16 *xhi, *xlo, *wThi, *wTlo;
    cudaGetSymbolAddress((void**)&xhi, g_xhi);
    cudaGetSymbolAddress((void**)&xlo, g_xlo);
    cudaGetSymbolAddress((void**)&wThi, g_wThi);
    cudaGetSymbolAddress((void**)&wTlo, g_wTlo);
    const size_t WSZ = (size_t)D_MODEL * D_MODEL;

    cudaFuncSetAttribute(gemm_mma, cudaFuncAttributeMaxDynamicSharedMemorySize, GEMM_SMEM);
    cudaFuncSetAttribute(gemm_tf32, cudaFuncAttributeMaxDynamicSharedMemorySize, TF32_SMEM);
    cudaFuncSetAttribute(attn_mma, cudaFuncAttributeMaxDynamicSharedMemorySize, ATTN_SMEM2);

    // x split (+ pos-norm tail block)
    split_fp32_pos<<<(MROWS * D_MODEL) / 256 + 1, 256>>>(x, xhi, xlo, posraw);
    // weight conversions
    dim3 gT3(D_MODEL / 32, D_MODEL / 32, 3);
    transpose_split3<<<gT3, 256>>>(wq, wk, wv, wThi, wTlo);
    dim3 gT1(D_MODEL / 32, D_MODEL / 32);
    transpose_tf32<<<gT1, 256>>>(wo, woT);

    // Fused Q/K/V projection (bf16 3-term, N = 3*D_MODEL)
    dim3 gQKV(3 * D_MODEL / 128, MROWS / 128);
    gemm_mma<<<gQKV, 256, GEMM_SMEM>>>(xhi, xlo, wThi, wTlo, qkv,
                                       MROWS, 3 * D_MODEL, D_MODEL);

    // RoPE + split + head-major reorder
    qkv_convert<<<(MROWS * N_HEADS * 64) / 256, 256>>>();

    // Flash attention -> fp32 (tf32-rounded) into g_qkv (buffer reuse)
    attn_mma<<<dim3(SEQ / 128, BATCH * N_HEADS), 256, ATTN_SMEM2>>>(qkv);

    // Output projection (tf32 single-pass)
    dim3 gG(D_MODEL / 128, MROWS / 128);
    gemm_tf32<<<gG, 256, TF32_SMEM>>>(qkv, woT, out, MROWS, D_MODEL, D_MODEL);
}